// round 2
// baseline (speedup 1.0000x reference)
#include <cuda_runtime.h>
#include <cuda_bf16.h>
#include <cstdint>

// Problem dims (fixed by the reference)
#define BDIM 4096
#define DDIM 768
#define FDIM 6144
#define CDIM 1000
#define KSEL 64

// Scratch (allocation-free rule: __device__ globals)
__device__ float g_h[(size_t)BDIM * FDIM];      // relu(x@W_inter + b)   96 MB
__device__ float g_vals[BDIM * KSEL];
__device__ int   g_idx [BDIM * KSEL];

// ---------------------------------------------------------------------------
// Kernel 1: accuracy-hardened fp32 SGEMM
//   C = relu(A[4096,768] @ B[768,6144] + bias)
// 128x128 block tile, 8x8 microtile, BK=16, 256 threads.
// Accumulation: fresh fp32 partial per 16-term k-chunk, merged into a
// Kahan-compensated (s,c) pair with __fadd_rn/__fsub_rn (cannot be
// reassociated by the compiler). Total accumulation error ~2e-7 (vs ~1.4e-6
// for sequential fp32) -> minimizes top-k boundary flips vs the reference.
// ---------------------------------------------------------------------------
__global__ void __launch_bounds__(256, 1) gemm_bias_relu(
    const float* __restrict__ A,     // [BDIM, DDIM]
    const float* __restrict__ B,     // [DDIM, FDIM]
    const float* __restrict__ bias)  // [FDIM]
{
    const int N = FDIM, K = DDIM;
    __shared__ float As[16][128];   // transposed A tile: As[k][m]
    __shared__ float Bs[16][128];   // Bs[k][n]

    const int tid = threadIdx.x;
    const int bm = blockIdx.y * 128;
    const int bn = blockIdx.x * 128;

    // A-load mapping: 128 rows x 16 cols = 512 float4, 2 per thread
    const int arow = tid >> 2;          // 0..63 (+64)
    const int acol = (tid & 3) * 4;     // 0,4,8,12
    // B-load mapping: 16 rows x 128 cols = 512 float4, 2 per thread
    const int brow = tid >> 5;          // 0..7 (+8)
    const int bcol = (tid & 31) * 4;    // 0..124

    const int tm = (tid >> 4) * 8;
    const int tn = (tid & 15) * 8;

    float s[8][8];      // compensated sum
    float comp[8][8];   // Kahan compensation
#pragma unroll
    for (int i = 0; i < 8; i++)
#pragma unroll
        for (int j = 0; j < 8; j++) { s[i][j] = 0.f; comp[i][j] = 0.f; }

    for (int k0 = 0; k0 < K; k0 += 16) {
#pragma unroll
        for (int r = 0; r < 128; r += 64) {
            float4 v = *(const float4*)&A[(size_t)(bm + arow + r) * K + k0 + acol];
            As[acol + 0][arow + r] = v.x;
            As[acol + 1][arow + r] = v.y;
            As[acol + 2][arow + r] = v.z;
            As[acol + 3][arow + r] = v.w;
        }
#pragma unroll
        for (int r = 0; r < 16; r += 8) {
            *(float4*)&Bs[brow + r][bcol] =
                *(const float4*)&B[(size_t)(k0 + brow + r) * N + bn + bcol];
        }
        __syncthreads();

        // fresh 16-term partial per accumulator
        float part[8][8];
#pragma unroll
        for (int i = 0; i < 8; i++)
#pragma unroll
            for (int j = 0; j < 8; j++) part[i][j] = 0.f;

#pragma unroll
        for (int kk = 0; kk < 16; kk++) {
            float ar[8], br[8];
            ((float4*)ar)[0] = *(const float4*)&As[kk][tm];
            ((float4*)ar)[1] = *(const float4*)&As[kk][tm + 4];
            ((float4*)br)[0] = *(const float4*)&Bs[kk][tn];
            ((float4*)br)[1] = *(const float4*)&Bs[kk][tn + 4];
#pragma unroll
            for (int i = 0; i < 8; i++)
#pragma unroll
                for (int j = 0; j < 8; j++)
                    part[i][j] = __fmaf_rn(ar[i], br[j], part[i][j]);
        }

        // Kahan merge of chunk partial into (s, comp)
#pragma unroll
        for (int i = 0; i < 8; i++)
#pragma unroll
            for (int j = 0; j < 8; j++) {
                float y = __fsub_rn(part[i][j], comp[i][j]);
                float t = __fadd_rn(s[i][j], y);
                comp[i][j] = __fsub_rn(__fsub_rn(t, s[i][j]), y);
                s[i][j] = t;
            }
        __syncthreads();
    }

    // epilogue: bias + relu (never emits -0), vectorized stores
    float bv[8];
    ((float4*)bv)[0] = *(const float4*)&bias[bn + tn];
    ((float4*)bv)[1] = *(const float4*)&bias[bn + tn + 4];
#pragma unroll
    for (int i = 0; i < 8; i++) {
        float o[8];
#pragma unroll
        for (int j = 0; j < 8; j++) {
            float v = __fadd_rn(s[i][j], bv[j]);
            o[j] = (v > 0.0f) ? v : 0.0f;   // select literal +0: no -0 possible
        }
        size_t base = (size_t)(bm + tm + i) * N + bn + tn;
        *(float4*)&g_h[base]     = ((float4*)o)[0];
        *(float4*)&g_h[base + 4] = ((float4*)o)[1];
    }
}

// ---------------------------------------------------------------------------
// Kernel 2: per-row top-64 via 4-pass byte radix select, write sparse row,
// record (vals, idx) for classifier. Values >= 0 so uint order == float order.
// Ties at the threshold taken in ascending index order (lax.top_k stability).
// ---------------------------------------------------------------------------
__global__ void __launch_bounds__(256) topk_kernel(float* __restrict__ sparse)
{
    const int F = FDIM;
    const int row = blockIdx.x;
    const int tid = threadIdx.x;

    __shared__ unsigned sh[FDIM];          // 24 KB
    __shared__ unsigned hist[256];
    __shared__ unsigned s_prefix, s_need, s_cnt, s_eqcnt;
    __shared__ unsigned eq_idx[64];

    const float* hrow = g_h + (size_t)row * F;
    for (int i = tid; i < F; i += 256) sh[i] = __float_as_uint(hrow[i]);
    if (tid == 0) { s_cnt = 0; s_eqcnt = 0; }
    __syncthreads();

    unsigned prefix = 0, need = KSEL;
    for (int level = 3; level >= 0; --level) {
        hist[tid] = 0;
        __syncthreads();
        const unsigned mask_hi = (level == 3) ? 0u : (0xFFFFFFFFu << ((level + 1) * 8));
        for (int i = tid; i < F; i += 256) {
            unsigned v = sh[i];
            if ((v & mask_hi) == (prefix & mask_hi)) {
                atomicAdd(&hist[(v >> (level * 8)) & 0xFFu], 1u);
            }
        }
        __syncthreads();
        if (tid == 0) {
            unsigned cum = 0;
            for (int b = 255; b >= 0; b--) {
                unsigned c = hist[b];
                if (cum + c >= need) {
                    s_need = need - cum;
                    s_prefix = prefix | ((unsigned)b << (level * 8));
                    break;
                }
                cum += c;
            }
        }
        __syncthreads();
        prefix = s_prefix;
        need = s_need;
        __syncthreads();
    }

    const unsigned T = prefix;               // exact threshold bit pattern
    const float Tval = __uint_as_float(T);
    float* srow = sparse + (size_t)row * F;
    float* vrow = g_vals + row * KSEL;
    int*   irow = g_idx  + row * KSEL;

    for (int i = tid; i < F; i += 256) {
        unsigned v = sh[i];
        float outv = 0.f;
        if (v > T) {
            outv = __uint_as_float(v);
            unsigned slot = atomicAdd(&s_cnt, 1u);
            vrow[slot] = outv;
            irow[slot] = i;
        } else if (v == T) {
            unsigned e = atomicAdd(&s_eqcnt, 1u);
            if (e < 64u) eq_idx[e] = (unsigned)i;
        }
        srow[i] = outv;
    }
    __syncthreads();

    if (tid == 0) {
        unsigned n_gt = s_cnt;                       // == KSEL - need by construction
        unsigned ne = min(s_eqcnt, 64u);
        // insertion sort ascending (ne is tiny, typically 1)
        for (unsigned a = 1; a < ne; a++) {
            unsigned key = eq_idx[a];
            int b = (int)a - 1;
            while (b >= 0 && eq_idx[b] > key) { eq_idx[b + 1] = eq_idx[b]; b--; }
            eq_idx[b + 1] = key;
        }
        for (unsigned a = 0; a < need; a++) {
            if (a < ne) {
                unsigned fi = eq_idx[a];
                srow[fi] = Tval;
                vrow[n_gt + a] = Tval;
                irow[n_gt + a] = (int)fi;
            } else {
                // only reachable when T == 0 (value contributes nothing)
                vrow[n_gt + a] = 0.f;
                irow[n_gt + a] = 0;
            }
        }
    }
}

// ---------------------------------------------------------------------------
// Kernel 3: logits[b,:] = b_cls + sum_j vals[b,j] * W_cls[idx[b,j], :]
// One block per row; 250 threads x 4 cols (float4). W_cls is L2-resident.
// ---------------------------------------------------------------------------
__global__ void __launch_bounds__(256) cls_kernel(
    const float* __restrict__ Wc,    // [FDIM, CDIM]
    const float* __restrict__ bc,    // [CDIM]
    float* __restrict__ logits)      // [BDIM, CDIM]
{
    const int row = blockIdx.x;
    const int tid = threadIdx.x;
    __shared__ float sv[KSEL];
    __shared__ int   si[KSEL];
    if (tid < KSEL) {
        sv[tid] = g_vals[row * KSEL + tid];
        si[tid] = g_idx [row * KSEL + tid];
    }
    __syncthreads();
    if (tid >= 250) return;
    const int c = tid * 4;
    float4 acc = *(const float4*)&bc[c];
#pragma unroll 4
    for (int j = 0; j < KSEL; j++) {
        const float v = sv[j];
        const float4 w = *(const float4*)&Wc[(size_t)si[j] * CDIM + c];
        acc.x = fmaf(v, w.x, acc.x);
        acc.y = fmaf(v, w.y, acc.y);
        acc.z = fmaf(v, w.z, acc.z);
        acc.w = fmaf(v, w.w, acc.w);
    }
    *(float4*)&logits[(size_t)row * CDIM + c] = acc;
}

// ---------------------------------------------------------------------------
extern "C" void kernel_launch(void* const* d_in, const int* in_sizes, int n_in,
                              void* d_out, int out_size)
{
    const float* x  = (const float*)d_in[0];   // [4096,768]
    const float* Wi = (const float*)d_in[1];   // [768,6144]
    const float* bi = (const float*)d_in[2];   // [6144]
    const float* Wc = (const float*)d_in[3];   // [6144,1000]
    const float* bc = (const float*)d_in[4];   // [1000]
    (void)in_sizes; (void)n_in; (void)out_size;

    float* sparse = (float*)d_out;                          // [4096,6144]
    float* logits = (float*)d_out + (size_t)BDIM * FDIM;    // [4096,1000]

    dim3 g1(FDIM / 128, BDIM / 128);      // 48 x 32
    gemm_bias_relu<<<g1, 256>>>(x, Wi, bi);
    topk_kernel<<<BDIM, 256>>>(sparse);
    cls_kernel<<<BDIM, 256>>>(Wc, bc, logits);
}

// round 3
// speedup vs baseline: 1.1429x; 1.1429x over previous
#include <cuda_runtime.h>
#include <cuda_bf16.h>
#include <cstdint>

// Problem dims (fixed by the reference)
#define BDIM 4096
#define DDIM 768
#define FDIM 6144
#define CDIM 1000
#define KSEL 64

typedef unsigned long long ull;

// Scratch (allocation-free rule: __device__ globals)
__device__ float g_h[(size_t)BDIM * FDIM];      // relu(x@W_inter + b)   96 MB
__device__ float g_vals[BDIM * KSEL];
__device__ int   g_idx [BDIM * KSEL];

// ---------------- f32x2 packed helpers (FFMA2) ------------------------------
__device__ __forceinline__ ull pack2(float x) {
    ull d; asm("mov.b64 %0, {%1, %1};" : "=l"(d) : "f"(x)); return d;
}
__device__ __forceinline__ ull fma2(ull a, ull b, ull c) {
    ull d; asm("fma.rn.f32x2 %0, %1, %2, %3;" : "=l"(d) : "l"(a), "l"(b), "l"(c)); return d;
}
__device__ __forceinline__ ull add2(ull a, ull b) {
    ull d; asm("add.rn.f32x2 %0, %1, %2;" : "=l"(d) : "l"(a), "l"(b)); return d;
}
// single-rounding a - b  ==  fma(b, -1.0, a)   (mul by -1 exact)
#define NEG1_F32X2 0xBF800000BF800000ULL
__device__ __forceinline__ ull sub2(ull a, ull b) { return fma2(b, NEG1_F32X2, a); }

__device__ __forceinline__ void unpack2(ull v, float& lo, float& hi) {
    asm("mov.b64 {%0, %1}, %2;" : "=f"(lo), "=f"(hi) : "l"(v));
}

// ---------------------------------------------------------------------------
// Kernel 1: accuracy-hardened fp32 SGEMM, f32x2-packed (FFMA2), double-buffered.
//   C = relu(A[4096,768] @ B[768,6144] + bias)
// 128x128 block tile, 8x8 microtile, BK=16, 256 threads.
// Numerics: BIT-IDENTICAL to the round-2 scalar Kahan-chunked version
// (fresh 16-term partial per k-chunk, Kahan merge; per-lane IEEE rounding of
// f32x2 equals scalar).
// ---------------------------------------------------------------------------
__global__ void __launch_bounds__(256, 1) gemm_bias_relu(
    const float* __restrict__ A,     // [BDIM, DDIM]
    const float* __restrict__ B,     // [DDIM, FDIM]
    const float* __restrict__ bias)  // [FDIM]
{
    const int N = FDIM, K = DDIM;
    __shared__ float As[2][16][128];   // As[buf][k][m]
    __shared__ float Bs[2][16][128];   // Bs[buf][k][n]

    const int tid = threadIdx.x;
    const int bm = blockIdx.y * 128;
    const int bn = blockIdx.x * 128;

    // A-load mapping: 128 rows x 16 cols = 512 float4, 2 per thread
    const int arow = tid >> 2;          // 0..63 (+64)
    const int acol = (tid & 3) * 4;     // 0,4,8,12
    // B-load mapping: 16 rows x 128 cols = 512 float4, 2 per thread
    const int brow = tid >> 5;          // 0..7 (+8)
    const int bcol = (tid & 31) * 4;    // 0..124

    const int tm = (tid >> 4) * 8;
    const int tn = (tid & 15) * 8;

    ull s2[8][4], c2[8][4];             // compensated sum + Kahan compensation
#pragma unroll
    for (int i = 0; i < 8; i++)
#pragma unroll
        for (int j = 0; j < 4; j++) { s2[i][j] = 0ULL; c2[i][j] = 0ULL; }

    const int NT = K / 16;              // 48 k-tiles

    // ---- prologue: tile 0 into buffer 0
    {
        float4 va0 = *(const float4*)&A[(size_t)(bm + arow) * K + acol];
        float4 va1 = *(const float4*)&A[(size_t)(bm + arow + 64) * K + acol];
        float4 vb0 = *(const float4*)&B[(size_t)(brow) * N + bn + bcol];
        float4 vb1 = *(const float4*)&B[(size_t)(brow + 8) * N + bn + bcol];
        As[0][acol + 0][arow] = va0.x; As[0][acol + 1][arow] = va0.y;
        As[0][acol + 2][arow] = va0.z; As[0][acol + 3][arow] = va0.w;
        As[0][acol + 0][arow + 64] = va1.x; As[0][acol + 1][arow + 64] = va1.y;
        As[0][acol + 2][arow + 64] = va1.z; As[0][acol + 3][arow + 64] = va1.w;
        *(float4*)&Bs[0][brow][bcol]     = vb0;
        *(float4*)&Bs[0][brow + 8][bcol] = vb1;
    }
    __syncthreads();

    for (int t = 0; t < NT; t++) {
        const int cur = t & 1;
        const int k0n = (t + 1) * 16;

        // issue next tile's global loads early
        float4 va0, va1, vb0, vb1;
        if (t + 1 < NT) {
            va0 = *(const float4*)&A[(size_t)(bm + arow) * K + k0n + acol];
            va1 = *(const float4*)&A[(size_t)(bm + arow + 64) * K + k0n + acol];
            vb0 = *(const float4*)&B[(size_t)(k0n + brow) * N + bn + bcol];
            vb1 = *(const float4*)&B[(size_t)(k0n + brow + 8) * N + bn + bcol];
        }

        // fresh 16-term partial per accumulator pair
        ull p2[8][4];
#pragma unroll
        for (int i = 0; i < 8; i++)
#pragma unroll
            for (int j = 0; j < 4; j++) p2[i][j] = 0ULL;

#pragma unroll
        for (int kk = 0; kk < 16; kk++) {
            float ar[8];
            ((float4*)ar)[0] = *(const float4*)&As[cur][kk][tm];
            ((float4*)ar)[1] = *(const float4*)&As[cur][kk][tm + 4];
            ull ar2[8];
#pragma unroll
            for (int i = 0; i < 8; i++) ar2[i] = pack2(ar[i]);
            ull br2[4];
            const ull* brp = (const ull*)&Bs[cur][kk][tn];
#pragma unroll
            for (int j = 0; j < 4; j++) br2[j] = brp[j];
#pragma unroll
            for (int i = 0; i < 8; i++)
#pragma unroll
                for (int j = 0; j < 4; j++)
                    p2[i][j] = fma2(ar2[i], br2[j], p2[i][j]);
        }

        // Kahan merge of chunk partial into (s, c)  [same op order as scalar]
#pragma unroll
        for (int i = 0; i < 8; i++)
#pragma unroll
            for (int j = 0; j < 4; j++) {
                ull y = sub2(p2[i][j], c2[i][j]);
                ull tt = add2(s2[i][j], y);
                c2[i][j] = sub2(sub2(tt, s2[i][j]), y);
                s2[i][j] = tt;
            }

        // stage next tile into the other buffer, then one sync
        if (t + 1 < NT) {
            const int nxt = cur ^ 1;
            As[nxt][acol + 0][arow] = va0.x; As[nxt][acol + 1][arow] = va0.y;
            As[nxt][acol + 2][arow] = va0.z; As[nxt][acol + 3][arow] = va0.w;
            As[nxt][acol + 0][arow + 64] = va1.x; As[nxt][acol + 1][arow + 64] = va1.y;
            As[nxt][acol + 2][arow + 64] = va1.z; As[nxt][acol + 3][arow + 64] = va1.w;
            *(float4*)&Bs[nxt][brow][bcol]     = vb0;
            *(float4*)&Bs[nxt][brow + 8][bcol] = vb1;
            __syncthreads();
        }
    }

    // epilogue: bias + relu (never emits -0), vectorized stores
    float bv[8];
    ((float4*)bv)[0] = *(const float4*)&bias[bn + tn];
    ((float4*)bv)[1] = *(const float4*)&bias[bn + tn + 4];
#pragma unroll
    for (int i = 0; i < 8; i++) {
        float o[8];
#pragma unroll
        for (int j = 0; j < 4; j++) {
            float lo, hi;
            unpack2(s2[i][j], lo, hi);
            float v0 = __fadd_rn(lo, bv[2 * j]);
            float v1 = __fadd_rn(hi, bv[2 * j + 1]);
            o[2 * j]     = (v0 > 0.0f) ? v0 : 0.0f;
            o[2 * j + 1] = (v1 > 0.0f) ? v1 : 0.0f;
        }
        size_t base = (size_t)(bm + tm + i) * N + bn + tn;
        *(float4*)&g_h[base]     = ((float4*)o)[0];
        *(float4*)&g_h[base + 4] = ((float4*)o)[1];
    }
}

// ---------------------------------------------------------------------------
// Kernel 2: per-row top-64 via 4-pass byte radix select, write sparse row,
// record (vals, idx) for classifier. Values >= 0 so uint order == float order.
// Ties at the threshold taken in ascending index order (lax.top_k stability).
// ---------------------------------------------------------------------------
__global__ void __launch_bounds__(256) topk_kernel(float* __restrict__ sparse)
{
    const int F = FDIM;
    const int row = blockIdx.x;
    const int tid = threadIdx.x;

    __shared__ unsigned sh[FDIM];          // 24 KB
    __shared__ unsigned hist[256];
    __shared__ unsigned s_prefix, s_need, s_cnt, s_eqcnt;
    __shared__ unsigned eq_idx[64];

    const float* hrow = g_h + (size_t)row * F;
    for (int i = tid; i < F; i += 256) sh[i] = __float_as_uint(hrow[i]);
    if (tid == 0) { s_cnt = 0; s_eqcnt = 0; }
    __syncthreads();

    unsigned prefix = 0, need = KSEL;
    for (int level = 3; level >= 0; --level) {
        hist[tid] = 0;
        __syncthreads();
        const unsigned mask_hi = (level == 3) ? 0u : (0xFFFFFFFFu << ((level + 1) * 8));
        for (int i = tid; i < F; i += 256) {
            unsigned v = sh[i];
            if ((v & mask_hi) == (prefix & mask_hi)) {
                atomicAdd(&hist[(v >> (level * 8)) & 0xFFu], 1u);
            }
        }
        __syncthreads();
        if (tid == 0) {
            unsigned cum = 0;
            for (int b = 255; b >= 0; b--) {
                unsigned c = hist[b];
                if (cum + c >= need) {
                    s_need = need - cum;
                    s_prefix = prefix | ((unsigned)b << (level * 8));
                    break;
                }
                cum += c;
            }
        }
        __syncthreads();
        prefix = s_prefix;
        need = s_need;
        __syncthreads();
    }

    const unsigned T = prefix;               // exact threshold bit pattern
    const float Tval = __uint_as_float(T);
    float* srow = sparse + (size_t)row * F;
    float* vrow = g_vals + row * KSEL;
    int*   irow = g_idx  + row * KSEL;

    for (int i = tid; i < F; i += 256) {
        unsigned v = sh[i];
        float outv = 0.f;
        if (v > T) {
            outv = __uint_as_float(v);
            unsigned slot = atomicAdd(&s_cnt, 1u);
            vrow[slot] = outv;
            irow[slot] = i;
        } else if (v == T) {
            unsigned e = atomicAdd(&s_eqcnt, 1u);
            if (e < 64u) eq_idx[e] = (unsigned)i;
        }
        srow[i] = outv;
    }
    __syncthreads();

    if (tid == 0) {
        unsigned n_gt = s_cnt;                       // == KSEL - need by construction
        unsigned ne = min(s_eqcnt, 64u);
        // insertion sort ascending (ne is tiny, typically 1)
        for (unsigned a = 1; a < ne; a++) {
            unsigned key = eq_idx[a];
            int b = (int)a - 1;
            while (b >= 0 && eq_idx[b] > key) { eq_idx[b + 1] = eq_idx[b]; b--; }
            eq_idx[b + 1] = key;
        }
        for (unsigned a = 0; a < need; a++) {
            if (a < ne) {
                unsigned fi = eq_idx[a];
                srow[fi] = Tval;
                vrow[n_gt + a] = Tval;
                irow[n_gt + a] = (int)fi;
            } else {
                // only reachable when T == 0 (value contributes nothing)
                vrow[n_gt + a] = 0.f;
                irow[n_gt + a] = 0;
            }
        }
    }
}

// ---------------------------------------------------------------------------
// Kernel 3: logits[b,:] = b_cls + sum_j vals[b,j] * W_cls[idx[b,j], :]
// One block per row; 250 threads x 4 cols (float4). W_cls is L2-resident.
// ---------------------------------------------------------------------------
__global__ void __launch_bounds__(256) cls_kernel(
    const float* __restrict__ Wc,    // [FDIM, CDIM]
    const float* __restrict__ bc,    // [CDIM]
    float* __restrict__ logits)      // [BDIM, CDIM]
{
    const int row = blockIdx.x;
    const int tid = threadIdx.x;
    __shared__ float sv[KSEL];
    __shared__ int   si[KSEL];
    if (tid < KSEL) {
        sv[tid] = g_vals[row * KSEL + tid];
        si[tid] = g_idx [row * KSEL + tid];
    }
    __syncthreads();
    if (tid >= 250) return;
    const int c = tid * 4;
    float4 acc = *(const float4*)&bc[c];
#pragma unroll 4
    for (int j = 0; j < KSEL; j++) {
        const float v = sv[j];
        const float4 w = *(const float4*)&Wc[(size_t)si[j] * CDIM + c];
        acc.x = fmaf(v, w.x, acc.x);
        acc.y = fmaf(v, w.y, acc.y);
        acc.z = fmaf(v, w.z, acc.z);
        acc.w = fmaf(v, w.w, acc.w);
    }
    *(float4*)&logits[(size_t)row * CDIM + c] = acc;
}

// ---------------------------------------------------------------------------
extern "C" void kernel_launch(void* const* d_in, const int* in_sizes, int n_in,
                              void* d_out, int out_size)
{
    const float* x  = (const float*)d_in[0];   // [4096,768]
    const float* Wi = (const float*)d_in[1];   // [768,6144]
    const float* bi = (const float*)d_in[2];   // [6144]
    const float* Wc = (const float*)d_in[3];   // [6144,1000]
    const float* bc = (const float*)d_in[4];   // [1000]
    (void)in_sizes; (void)n_in; (void)out_size;

    float* sparse = (float*)d_out;                          // [4096,6144]
    float* logits = (float*)d_out + (size_t)BDIM * FDIM;    // [4096,1000]

    dim3 g1(FDIM / 128, BDIM / 128);      // 48 x 32
    gemm_bias_relu<<<g1, 256>>>(x, Wi, bi);
    topk_kernel<<<BDIM, 256>>>(sparse);
    cls_kernel<<<BDIM, 256>>>(Wc, bc, logits);
}

// round 4
// speedup vs baseline: 1.1433x; 1.0004x over previous
#include <cuda_runtime.h>
#include <cuda_bf16.h>
#include <cstdint>

// Problem dims (fixed by the reference)
#define BDIM 4096
#define DDIM 768
#define FDIM 6144
#define CDIM 1000
#define KSEL 64

typedef unsigned long long ull;

// Scratch (allocation-free rule: __device__ globals)
__device__ float g_h[(size_t)BDIM * FDIM];      // relu(x@W_inter + b)   96 MB
__device__ float g_vals[BDIM * KSEL];
__device__ int   g_idx [BDIM * KSEL];

// ---------------- f32x2 packed helpers (FFMA2) ------------------------------
__device__ __forceinline__ ull pack2(float x) {
    ull d; asm("mov.b64 %0, {%1, %1};" : "=l"(d) : "f"(x)); return d;
}
__device__ __forceinline__ ull fma2(ull a, ull b, ull c) {
    ull d; asm("fma.rn.f32x2 %0, %1, %2, %3;" : "=l"(d) : "l"(a), "l"(b), "l"(c)); return d;
}
__device__ __forceinline__ ull add2(ull a, ull b) {
    ull d; asm("add.rn.f32x2 %0, %1, %2;" : "=l"(d) : "l"(a), "l"(b)); return d;
}
// single-rounding a - b  ==  fma(b, -1.0, a)   (mul by -1 exact)
#define NEG1_F32X2 0xBF800000BF800000ULL
__device__ __forceinline__ ull sub2(ull a, ull b) { return fma2(b, NEG1_F32X2, a); }

__device__ __forceinline__ void unpack2(ull v, float& lo, float& hi) {
    asm("mov.b64 {%0, %1}, %2;" : "=f"(lo), "=f"(hi) : "l"(v));
}

// ---------------------------------------------------------------------------
// Kernel 1: accuracy-hardened fp32 SGEMM, f32x2-packed (FFMA2), double-buffered.
//   C = relu(A[4096,768] @ B[768,6144] + bias)
// 128x128 block tile, 8x8 microtile, BK=16, 256 threads.
// Numerics: BIT-IDENTICAL to the round-2 scalar Kahan-chunked version
// (fresh 16-term partial per k-chunk, Kahan merge; per-lane IEEE rounding of
// f32x2 equals scalar).
// ---------------------------------------------------------------------------
__global__ void __launch_bounds__(256, 1) gemm_bias_relu(
    const float* __restrict__ A,     // [BDIM, DDIM]
    const float* __restrict__ B,     // [DDIM, FDIM]
    const float* __restrict__ bias)  // [FDIM]
{
    const int N = FDIM, K = DDIM;
    __shared__ float As[2][16][128];   // As[buf][k][m]
    __shared__ float Bs[2][16][128];   // Bs[buf][k][n]

    const int tid = threadIdx.x;
    const int bm = blockIdx.y * 128;
    const int bn = blockIdx.x * 128;

    // A-load mapping: 128 rows x 16 cols = 512 float4, 2 per thread
    const int arow = tid >> 2;          // 0..63 (+64)
    const int acol = (tid & 3) * 4;     // 0,4,8,12
    // B-load mapping: 16 rows x 128 cols = 512 float4, 2 per thread
    const int brow = tid >> 5;          // 0..7 (+8)
    const int bcol = (tid & 31) * 4;    // 0..124

    const int tm = (tid >> 4) * 8;
    const int tn = (tid & 15) * 8;

    ull s2[8][4], c2[8][4];             // compensated sum + Kahan compensation
#pragma unroll
    for (int i = 0; i < 8; i++)
#pragma unroll
        for (int j = 0; j < 4; j++) { s2[i][j] = 0ULL; c2[i][j] = 0ULL; }

    const int NT = K / 16;              // 48 k-tiles

    // ---- prologue: tile 0 into buffer 0
    {
        float4 va0 = *(const float4*)&A[(size_t)(bm + arow) * K + acol];
        float4 va1 = *(const float4*)&A[(size_t)(bm + arow + 64) * K + acol];
        float4 vb0 = *(const float4*)&B[(size_t)(brow) * N + bn + bcol];
        float4 vb1 = *(const float4*)&B[(size_t)(brow + 8) * N + bn + bcol];
        As[0][acol + 0][arow] = va0.x; As[0][acol + 1][arow] = va0.y;
        As[0][acol + 2][arow] = va0.z; As[0][acol + 3][arow] = va0.w;
        As[0][acol + 0][arow + 64] = va1.x; As[0][acol + 1][arow + 64] = va1.y;
        As[0][acol + 2][arow + 64] = va1.z; As[0][acol + 3][arow + 64] = va1.w;
        *(float4*)&Bs[0][brow][bcol]     = vb0;
        *(float4*)&Bs[0][brow + 8][bcol] = vb1;
    }
    __syncthreads();

    for (int t = 0; t < NT; t++) {
        const int cur = t & 1;
        const int k0n = (t + 1) * 16;

        // issue next tile's global loads early
        float4 va0, va1, vb0, vb1;
        if (t + 1 < NT) {
            va0 = *(const float4*)&A[(size_t)(bm + arow) * K + k0n + acol];
            va1 = *(const float4*)&A[(size_t)(bm + arow + 64) * K + k0n + acol];
            vb0 = *(const float4*)&B[(size_t)(k0n + brow) * N + bn + bcol];
            vb1 = *(const float4*)&B[(size_t)(k0n + brow + 8) * N + bn + bcol];
        }

        // fresh 16-term partial per accumulator pair
        ull p2[8][4];
#pragma unroll
        for (int i = 0; i < 8; i++)
#pragma unroll
            for (int j = 0; j < 4; j++) p2[i][j] = 0ULL;

#pragma unroll
        for (int kk = 0; kk < 16; kk++) {
            float ar[8];
            ((float4*)ar)[0] = *(const float4*)&As[cur][kk][tm];
            ((float4*)ar)[1] = *(const float4*)&As[cur][kk][tm + 4];
            ull ar2[8];
#pragma unroll
            for (int i = 0; i < 8; i++) ar2[i] = pack2(ar[i]);
            ull br2[4];
            const ull* brp = (const ull*)&Bs[cur][kk][tn];
#pragma unroll
            for (int j = 0; j < 4; j++) br2[j] = brp[j];
#pragma unroll
            for (int i = 0; i < 8; i++)
#pragma unroll
                for (int j = 0; j < 4; j++)
                    p2[i][j] = fma2(ar2[i], br2[j], p2[i][j]);
        }

        // Kahan merge of chunk partial into (s, c)  [same op order as scalar]
#pragma unroll
        for (int i = 0; i < 8; i++)
#pragma unroll
            for (int j = 0; j < 4; j++) {
                ull y = sub2(p2[i][j], c2[i][j]);
                ull tt = add2(s2[i][j], y);
                c2[i][j] = sub2(sub2(tt, s2[i][j]), y);
                s2[i][j] = tt;
            }

        // stage next tile into the other buffer, then one sync
        if (t + 1 < NT) {
            const int nxt = cur ^ 1;
            As[nxt][acol + 0][arow] = va0.x; As[nxt][acol + 1][arow] = va0.y;
            As[nxt][acol + 2][arow] = va0.z; As[nxt][acol + 3][arow] = va0.w;
            As[nxt][acol + 0][arow + 64] = va1.x; As[nxt][acol + 1][arow + 64] = va1.y;
            As[nxt][acol + 2][arow + 64] = va1.z; As[nxt][acol + 3][arow + 64] = va1.w;
            *(float4*)&Bs[nxt][brow][bcol]     = vb0;
            *(float4*)&Bs[nxt][brow + 8][bcol] = vb1;
            __syncthreads();
        }
    }

    // epilogue: bias + relu (never emits -0), vectorized stores
    float bv[8];
    ((float4*)bv)[0] = *(const float4*)&bias[bn + tn];
    ((float4*)bv)[1] = *(const float4*)&bias[bn + tn + 4];
#pragma unroll
    for (int i = 0; i < 8; i++) {
        float o[8];
#pragma unroll
        for (int j = 0; j < 4; j++) {
            float lo, hi;
            unpack2(s2[i][j], lo, hi);
            float v0 = __fadd_rn(lo, bv[2 * j]);
            float v1 = __fadd_rn(hi, bv[2 * j + 1]);
            o[2 * j]     = (v0 > 0.0f) ? v0 : 0.0f;
            o[2 * j + 1] = (v1 > 0.0f) ? v1 : 0.0f;
        }
        size_t base = (size_t)(bm + tm + i) * N + bn + tn;
        *(float4*)&g_h[base]     = ((float4*)o)[0];
        *(float4*)&g_h[base + 4] = ((float4*)o)[1];
    }
}

// ---------------------------------------------------------------------------
// Kernel 2: per-row top-64 via 4-pass byte radix select, write sparse row,
// record (vals, idx) for classifier. Values >= 0 so uint order == float order.
// Ties at the threshold taken in ascending index order (lax.top_k stability).
// ---------------------------------------------------------------------------
__global__ void __launch_bounds__(256) topk_kernel(float* __restrict__ sparse)
{
    const int F = FDIM;
    const int row = blockIdx.x;
    const int tid = threadIdx.x;

    __shared__ unsigned sh[FDIM];          // 24 KB
    __shared__ unsigned hist[256];
    __shared__ unsigned s_prefix, s_need, s_cnt, s_eqcnt;
    __shared__ unsigned eq_idx[64];

    const float* hrow = g_h + (size_t)row * F;
    for (int i = tid; i < F; i += 256) sh[i] = __float_as_uint(hrow[i]);
    if (tid == 0) { s_cnt = 0; s_eqcnt = 0; }
    __syncthreads();

    unsigned prefix = 0, need = KSEL;
    for (int level = 3; level >= 0; --level) {
        hist[tid] = 0;
        __syncthreads();
        const unsigned mask_hi = (level == 3) ? 0u : (0xFFFFFFFFu << ((level + 1) * 8));
        for (int i = tid; i < F; i += 256) {
            unsigned v = sh[i];
            if ((v & mask_hi) == (prefix & mask_hi)) {
                atomicAdd(&hist[(v >> (level * 8)) & 0xFFu], 1u);
            }
        }
        __syncthreads();
        if (tid == 0) {
            unsigned cum = 0;
            for (int b = 255; b >= 0; b--) {
                unsigned c = hist[b];
                if (cum + c >= need) {
                    s_need = need - cum;
                    s_prefix = prefix | ((unsigned)b << (level * 8));
                    break;
                }
                cum += c;
            }
        }
        __syncthreads();
        prefix = s_prefix;
        need = s_need;
        __syncthreads();
    }

    const unsigned T = prefix;               // exact threshold bit pattern
    const float Tval = __uint_as_float(T);
    float* srow = sparse + (size_t)row * F;
    float* vrow = g_vals + row * KSEL;
    int*   irow = g_idx  + row * KSEL;

    for (int i = tid; i < F; i += 256) {
        unsigned v = sh[i];
        float outv = 0.f;
        if (v > T) {
            outv = __uint_as_float(v);
            unsigned slot = atomicAdd(&s_cnt, 1u);
            vrow[slot] = outv;
            irow[slot] = i;
        } else if (v == T) {
            unsigned e = atomicAdd(&s_eqcnt, 1u);
            if (e < 64u) eq_idx[e] = (unsigned)i;
        }
        srow[i] = outv;
    }
    __syncthreads();

    if (tid == 0) {
        unsigned n_gt = s_cnt;                       // == KSEL - need by construction
        unsigned ne = min(s_eqcnt, 64u);
        // insertion sort ascending (ne is tiny, typically 1)
        for (unsigned a = 1; a < ne; a++) {
            unsigned key = eq_idx[a];
            int b = (int)a - 1;
            while (b >= 0 && eq_idx[b] > key) { eq_idx[b + 1] = eq_idx[b]; b--; }
            eq_idx[b + 1] = key;
        }
        for (unsigned a = 0; a < need; a++) {
            if (a < ne) {
                unsigned fi = eq_idx[a];
                srow[fi] = Tval;
                vrow[n_gt + a] = Tval;
                irow[n_gt + a] = (int)fi;
            } else {
                // only reachable when T == 0 (value contributes nothing)
                vrow[n_gt + a] = 0.f;
                irow[n_gt + a] = 0;
            }
        }
    }
}

// ---------------------------------------------------------------------------
// Kernel 3: logits[b,:] = b_cls + sum_j vals[b,j] * W_cls[idx[b,j], :]
// One block per row; 250 threads x 4 cols (float4). W_cls is L2-resident.
// ---------------------------------------------------------------------------
__global__ void __launch_bounds__(256) cls_kernel(
    const float* __restrict__ Wc,    // [FDIM, CDIM]
    const float* __restrict__ bc,    // [CDIM]
    float* __restrict__ logits)      // [BDIM, CDIM]
{
    const int row = blockIdx.x;
    const int tid = threadIdx.x;
    __shared__ float sv[KSEL];
    __shared__ int   si[KSEL];
    if (tid < KSEL) {
        sv[tid] = g_vals[row * KSEL + tid];
        si[tid] = g_idx [row * KSEL + tid];
    }
    __syncthreads();
    if (tid >= 250) return;
    const int c = tid * 4;
    float4 acc = *(const float4*)&bc[c];
#pragma unroll 4
    for (int j = 0; j < KSEL; j++) {
        const float v = sv[j];
        const float4 w = *(const float4*)&Wc[(size_t)si[j] * CDIM + c];
        acc.x = fmaf(v, w.x, acc.x);
        acc.y = fmaf(v, w.y, acc.y);
        acc.z = fmaf(v, w.z, acc.z);
        acc.w = fmaf(v, w.w, acc.w);
    }
    *(float4*)&logits[(size_t)row * CDIM + c] = acc;
}

// ---------------------------------------------------------------------------
extern "C" void kernel_launch(void* const* d_in, const int* in_sizes, int n_in,
                              void* d_out, int out_size)
{
    const float* x  = (const float*)d_in[0];   // [4096,768]
    const float* Wi = (const float*)d_in[1];   // [768,6144]
    const float* bi = (const float*)d_in[2];   // [6144]
    const float* Wc = (const float*)d_in[3];   // [6144,1000]
    const float* bc = (const float*)d_in[4];   // [1000]
    (void)in_sizes; (void)n_in; (void)out_size;

    float* sparse = (float*)d_out;                          // [4096,6144]
    float* logits = (float*)d_out + (size_t)BDIM * FDIM;    // [4096,1000]

    dim3 g1(FDIM / 128, BDIM / 128);      // 48 x 32
    gemm_bias_relu<<<g1, 256>>>(x, Wi, bi);
    topk_kernel<<<BDIM, 256>>>(sparse);
    cls_kernel<<<BDIM, 256>>>(Wc, bc, logits);
}

// round 6
// speedup vs baseline: 2.4292x; 2.1246x over previous
#include <cuda_runtime.h>
#include <cuda_bf16.h>
#include <cstdint>

#define BDIM 4096
#define DDIM 768
#define FDIM 6144
#define CDIM 1000
#define KSEL 64

// ---- mma-GEMM tiling --------------------------------------------------------
#define KC2 32
#define NCH (DDIM / KC2)          // 24
#define ROWBYTES 80               // 32 bf16 (64B) + 16B pad: conflict-free ldmatrix
#define TILEB (128 * ROWBYTES)    // 10240 B
#define BUFB (4 * TILEB)          // Ah, Am, Bh, Bm
#define SMEMDYN (2 * BUFB)        // 81920 B

#define MAXFLAG 4096
#define CAND_MAX 64
#define GAP_TAU 3e-4f

// ---- scratch ------------------------------------------------------------------
__device__ float g_h[(size_t)BDIM * FDIM];
__device__ float g_vals[BDIM * KSEL];
__device__ int   g_idx [BDIM * KSEL];
__device__ unsigned g_T[BDIM];
__device__ unsigned g_nflag;
__device__ int   g_flagrows[MAXFLAG];
__device__ __nv_bfloat16 gAh[(size_t)BDIM * DDIM];
__device__ __nv_bfloat16 gAm[(size_t)BDIM * DDIM];
__device__ __nv_bfloat16 gBh[(size_t)FDIM * DDIM];   // W_inter^T limbs, [n][k]
__device__ __nv_bfloat16 gBm[(size_t)FDIM * DDIM];

// ---- helpers -------------------------------------------------------------------
__device__ __forceinline__ uint32_t smem_u32(const void* p) {
    uint32_t a;
    asm("{ .reg .u64 t; cvta.to.shared.u64 t, %1; cvt.u32.u64 %0, t; }" : "=r"(a) : "l"(p));
    return a;
}
__device__ __forceinline__ void cp_async16(uint32_t dst, const void* src) {
    asm volatile("cp.async.cg.shared.global [%0], [%1], 16;" :: "r"(dst), "l"(src));
}
__device__ __forceinline__ void ldsm4(uint32_t* r, uint32_t addr) {
    asm volatile("ldmatrix.sync.aligned.m8n8.x4.shared.b16 {%0,%1,%2,%3}, [%4];"
                 : "=r"(r[0]), "=r"(r[1]), "=r"(r[2]), "=r"(r[3]) : "r"(addr));
}
__device__ __forceinline__ void mma16816(float* d, const uint32_t* a, const uint32_t* b) {
    asm volatile("mma.sync.aligned.m16n8k16.row.col.f32.bf16.bf16.f32 "
                 "{%0,%1,%2,%3}, {%4,%5,%6,%7}, {%8,%9}, {%0,%1,%2,%3};"
                 : "+f"(d[0]), "+f"(d[1]), "+f"(d[2]), "+f"(d[3])
                 : "r"(a[0]), "r"(a[1]), "r"(a[2]), "r"(a[3]), "r"(b[0]), "r"(b[1]));
}

// ---- split kernels: exact 2-limb bf16 decomposition -----------------------------
__global__ void split_A(const float* __restrict__ x)
{
    if (blockIdx.x == 0 && threadIdx.x == 0) g_nflag = 0;
    const size_t n = (size_t)BDIM * DDIM;
    for (size_t i = (size_t)blockIdx.x * blockDim.x + threadIdx.x; i < n;
         i += (size_t)gridDim.x * blockDim.x) {
        float v = x[i];
        __nv_bfloat16 h = __float2bfloat16_rn(v);
        float r1 = v - __bfloat162float(h);
        gAh[i] = h; gAm[i] = __float2bfloat16_rn(r1);
    }
}

__global__ void __launch_bounds__(256) split_BT(const float* __restrict__ W)
{
    __shared__ float t[32][33];
    const int n0 = blockIdx.x * 32, k0 = blockIdx.y * 32;
    const int tx = threadIdx.x & 31, ty = threadIdx.x >> 5;
#pragma unroll
    for (int i = 0; i < 32; i += 8)
        t[ty + i][tx] = W[(size_t)(k0 + ty + i) * FDIM + n0 + tx];
    __syncthreads();
#pragma unroll
    for (int i = 0; i < 32; i += 8) {
        float v = t[tx][ty + i];
        __nv_bfloat16 h = __float2bfloat16_rn(v);
        float r1 = v - __bfloat162float(h);
        size_t o = (size_t)(n0 + ty + i) * DDIM + k0 + tx;
        gBh[o] = h; gBm[o] = __float2bfloat16_rn(r1);
    }
}

// ---- tensor-core GEMM: h = relu(x @ W + b), bf16x3 -------------------------------
__device__ __forceinline__ void load_tiles(uint32_t sbase, int buf, int ch,
                                           int bm, int bn, int tid)
{
    const uint32_t bb = sbase + buf * BUFB;
    const int k0 = ch * KC2;
    const __nv_bfloat16* srcs[4] = { gAh, gAm, gBh, gBm };
#pragma unroll
    for (int t = 0; t < 4; t++) {
        const int rbase = (t < 2) ? bm : bn;
        const __nv_bfloat16* sp = srcs[t] + (size_t)rbase * DDIM + k0;
        const uint32_t tb = bb + t * TILEB;
#pragma unroll
        for (int i = tid; i < 512; i += 256) {
            const int row = i >> 2, seg = i & 3;
            cp_async16(tb + row * ROWBYTES + seg * 16, sp + (size_t)row * DDIM + seg * 8);
        }
    }
    asm volatile("cp.async.commit_group;" ::: "memory");
}

__global__ void __launch_bounds__(256, 1) mma_gemm(const float* __restrict__ bias)
{
    extern __shared__ char dsm[];
    const uint32_t sbase = smem_u32(dsm);
    const int tid = threadIdx.x, wid = tid >> 5, lane = tid & 31;
    const int bm = blockIdx.y * 128, bn = blockIdx.x * 128;
    const int wm = (wid >> 2) * 64;   // 0 / 64
    const int wn = (wid & 3) * 32;    // 0..96

    float d[4][4][4];
#pragma unroll
    for (int i = 0; i < 4; i++)
#pragma unroll
        for (int j = 0; j < 4; j++)
#pragma unroll
            for (int q = 0; q < 4; q++) d[i][j][q] = 0.f;

    load_tiles(sbase, 0, 0, bm, bn, tid);
    load_tiles(sbase, 1, 1, bm, bn, tid);

    // per-thread ldmatrix offsets within a tile
    const uint32_t aoff = (uint32_t)(wm + (lane & 15)) * ROWBYTES + ((lane >> 4) * 8) * 2;
    const uint32_t boff = (uint32_t)(wn + ((lane >> 4) & 1) * 8 + (lane & 7)) * ROWBYTES
                        + (((lane >> 3) & 1) * 8) * 2;

#pragma unroll 1
    for (int ch = 0; ch < NCH; ch++) {
        const int buf = ch & 1;
        if (ch < NCH - 1) asm volatile("cp.async.wait_group 1;" ::: "memory");
        else              asm volatile("cp.async.wait_group 0;" ::: "memory");
        __syncthreads();

        const uint32_t bb = sbase + buf * BUFB;
#pragma unroll
        for (int kk = 0; kk < 2; kk++) {
            const uint32_t ko = kk * 32;            // 16 bf16 = 32 B
            uint32_t ah[4][4], am[4][4], bh[2][4], bmm[2][4];
#pragma unroll
            for (int ma = 0; ma < 4; ma++) {
                ldsm4(ah[ma], bb + 0 * TILEB + aoff + ma * 16 * ROWBYTES + ko);
                ldsm4(am[ma], bb + 1 * TILEB + aoff + ma * 16 * ROWBYTES + ko);
            }
#pragma unroll
            for (int pr = 0; pr < 2; pr++) {
                ldsm4(bh[pr],  bb + 2 * TILEB + boff + pr * 16 * ROWBYTES + ko);
                ldsm4(bmm[pr], bb + 3 * TILEB + boff + pr * 16 * ROWBYTES + ko);
            }
#pragma unroll
            for (int ma = 0; ma < 4; ma++)
#pragma unroll
                for (int na = 0; na < 4; na++) {
                    const uint32_t* bhf = &bh[na >> 1][(na & 1) * 2];
                    const uint32_t* bmf = &bmm[na >> 1][(na & 1) * 2];
                    mma16816(d[ma][na], ah[ma], bhf);   // h*h
                    mma16816(d[ma][na], ah[ma], bmf);   // h*m
                    mma16816(d[ma][na], am[ma], bhf);   // m*h
                }
        }
        __syncthreads();
        if (ch + 2 < NCH) load_tiles(sbase, buf, ch + 2, bm, bn, tid);
    }

    // epilogue: bias + relu (never -0)
#pragma unroll
    for (int na = 0; na < 4; na++) {
        const int n0g = bn + wn + na * 8 + (lane & 3) * 2;
        const float b0 = bias[n0g], b1 = bias[n0g + 1];
#pragma unroll
        for (int ma = 0; ma < 4; ma++) {
            const int m0g = bm + wm + ma * 16 + (lane >> 2);
            float v0 = __fadd_rn(d[ma][na][0], b0);
            float v1 = __fadd_rn(d[ma][na][1], b1);
            float v2 = __fadd_rn(d[ma][na][2], b0);
            float v3 = __fadd_rn(d[ma][na][3], b1);
            float2 o0 = { (v0 > 0.f) ? v0 : 0.f, (v1 > 0.f) ? v1 : 0.f };
            float2 o1 = { (v2 > 0.f) ? v2 : 0.f, (v3 > 0.f) ? v3 : 0.f };
            *(float2*)&g_h[(size_t)m0g * FDIM + n0g]       = o0;
            *(float2*)&g_h[(size_t)(m0g + 8) * FDIM + n0g] = o1;
        }
    }
}

// ---- top-64 radix select + ambiguity flagging -----------------------------------
__global__ void __launch_bounds__(256) topk_kernel(float* __restrict__ sparse)
{
    const int F = FDIM;
    const int row = blockIdx.x;
    const int tid = threadIdx.x;

    __shared__ unsigned sh[FDIM];
    __shared__ unsigned hist[256];
    __shared__ unsigned s_prefix, s_need, s_cnt, s_eqcnt, s_below;
    __shared__ unsigned eq_idx[64];

    const float* hrow = g_h + (size_t)row * F;
    for (int i = tid; i < F; i += 256) sh[i] = __float_as_uint(hrow[i]);
    if (tid == 0) { s_cnt = 0; s_eqcnt = 0; s_below = 0; }
    __syncthreads();

    unsigned prefix = 0, need = KSEL;
    for (int level = 3; level >= 0; --level) {
        hist[tid] = 0;
        __syncthreads();
        const unsigned mask_hi = (level == 3) ? 0u : (0xFFFFFFFFu << ((level + 1) * 8));
        for (int i = tid; i < F; i += 256) {
            unsigned v = sh[i];
            if ((v & mask_hi) == (prefix & mask_hi))
                atomicAdd(&hist[(v >> (level * 8)) & 0xFFu], 1u);
        }
        __syncthreads();
        if (tid == 0) {
            unsigned cum = 0;
            for (int b = 255; b >= 0; b--) {
                unsigned c = hist[b];
                if (cum + c >= need) {
                    s_need = need - cum;
                    s_prefix = prefix | ((unsigned)b << (level * 8));
                    break;
                }
                cum += c;
            }
        }
        __syncthreads();
        prefix = s_prefix;
        need = s_need;
        __syncthreads();
    }

    const unsigned T = prefix;
    const float Tval = __uint_as_float(T);
    float* srow = sparse + (size_t)row * F;
    float* vrow = g_vals + row * KSEL;
    int*   irow = g_idx  + row * KSEL;

    unsigned lm = 0;
    for (int i = tid; i < F; i += 256) {
        unsigned v = sh[i];
        float outv = 0.f;
        if (v > T) {
            outv = __uint_as_float(v);
            unsigned slot = atomicAdd(&s_cnt, 1u);
            vrow[slot] = outv;
            irow[slot] = i;
        } else if (v == T) {
            unsigned e = atomicAdd(&s_eqcnt, 1u);
            if (e < 64u) eq_idx[e] = (unsigned)i;
        } else {
            lm = max(lm, v);
        }
        srow[i] = outv;
    }
#pragma unroll
    for (int o = 16; o; o >>= 1) lm = max(lm, __shfl_xor_sync(0xFFFFFFFFu, lm, o));
    if ((tid & 31) == 0) atomicMax(&s_below, lm);
    __syncthreads();

    if (tid == 0) {
        unsigned n_gt = s_cnt;
        unsigned ne = min(s_eqcnt, 64u);
        for (unsigned a = 1; a < ne; a++) {
            unsigned key = eq_idx[a];
            int b = (int)a - 1;
            while (b >= 0 && eq_idx[b] > key) { eq_idx[b + 1] = eq_idx[b]; b--; }
            eq_idx[b + 1] = key;
        }
        for (unsigned a = 0; a < need; a++) {
            if (a < ne) {
                unsigned fi = eq_idx[a];
                srow[fi] = Tval;
                vrow[n_gt + a] = Tval;
                irow[n_gt + a] = (int)fi;
            } else {
                vrow[n_gt + a] = 0.f;
                irow[n_gt + a] = 0;
            }
        }
        g_T[row] = T;
        bool spill = (s_eqcnt > need);
        float below = __uint_as_float(s_below);
        if (T != 0u && (spill || (Tval - below) < GAP_TAU)) {
            unsigned p = atomicAdd(&g_nflag, 1u);
            if (p < MAXFLAG) g_flagrows[p] = row;
        }
    }
}

// ---- exact repair of flagged rows -------------------------------------------------
__global__ void __launch_bounds__(256) repair_kernel(
    const float* __restrict__ x, const float* __restrict__ Wi,
    const float* __restrict__ bi, float* __restrict__ sparse)
{
    __shared__ float xs[DDIM];
    __shared__ int   cand[CAND_MAX];
    __shared__ float cex[CAND_MAX];
    __shared__ float red[256];
    __shared__ unsigned s_nc, s_nhi;

    unsigned nf = min(g_nflag, (unsigned)MAXFLAG);
    if (blockIdx.x >= nf) return;
    const int row = g_flagrows[blockIdx.x];
    const int tid = threadIdx.x;
    const float Tval = __uint_as_float(g_T[row]);
    const float* hrow = g_h + (size_t)row * FDIM;

    for (int i = tid; i < DDIM; i += 256) xs[i] = x[(size_t)row * DDIM + i];
    if (tid == 0) { s_nc = 0; s_nhi = 0; }
    __syncthreads();

    unsigned nhi_loc = 0;
    for (int f = tid; f < FDIM; f += 256) {
        float v = hrow[f];
        if (fabsf(v - Tval) <= GAP_TAU) {
            unsigned p = atomicAdd(&s_nc, 1u);
            if (p < CAND_MAX) cand[p] = f;
        } else if (v > Tval) nhi_loc++;
    }
    atomicAdd(&s_nhi, nhi_loc);
    __syncthreads();
    const unsigned nc = s_nc;
    if (nc > CAND_MAX) return;   // practically impossible

    for (unsigned j = 0; j < nc; j++) {
        const int f = cand[j];
        float s = 0.f, c = 0.f;
        for (int d = tid; d < DDIM; d += 256) {
            float p = __fmaf_rn(xs[d], Wi[(size_t)d * FDIM + f], 0.f);
            float y = __fsub_rn(p, c);
            float t2 = __fadd_rn(s, y);
            c = __fsub_rn(__fsub_rn(t2, s), y);
            s = t2;
        }
        red[tid] = s;
        __syncthreads();
        for (int o = 128; o > 0; o >>= 1) {
            if (tid < o) red[tid] = __fadd_rn(red[tid], red[tid + o]);
            __syncthreads();
        }
        if (tid == 0) {
            float v = __fadd_rn(red[0], bi[f]);
            cex[j] = (v > 0.f) ? v : 0.f;
        }
        __syncthreads();
    }
    if (tid != 0) return;

    float* srow = sparse + (size_t)row * FDIM;
    float* vrow = g_vals + row * KSEL;
    int*   irow = g_idx  + row * KSEL;

    int k_rem = KSEL - (int)s_nhi;
    bool want[CAND_MAX], cur[CAND_MAX];
    for (unsigned j = 0; j < nc; j++) {
        want[j] = false;
        cur[j] = (srow[cand[j]] != 0.f);
    }
    for (int slot = 0; slot < k_rem; slot++) {
        int best = -1;
        for (unsigned j = 0; j < nc; j++) {
            if (want[j]) continue;
            if (best < 0 || cex[j] > cex[best] ||
                (cex[j] == cex[best] && cand[j] < cand[best])) best = (int)j;
        }
        if (best >= 0) want[best] = true;
    }
    int addq[CAND_MAX]; int na = 0;
    for (unsigned j = 0; j < nc; j++) if (want[j] && !cur[j]) addq[na++] = (int)j;
    int ai = 0;
    for (unsigned j = 0; j < nc && ai < na; j++) {
        if (cur[j] && !want[j]) {
            int rf = cand[j];
            int af = cand[addq[ai]]; ai++;
            float av = hrow[af];
            srow[rf] = 0.f;
            srow[af] = av;
            for (int q = 0; q < KSEL; q++)
                if (irow[q] == rf) { irow[q] = af; vrow[q] = av; break; }
        }
    }
}

// ---- classifier ---------------------------------------------------------------------
__global__ void __launch_bounds__(256) cls_kernel(
    const float* __restrict__ Wc, const float* __restrict__ bc,
    float* __restrict__ logits)
{
    const int row = blockIdx.x;
    const int tid = threadIdx.x;
    __shared__ float sv[KSEL];
    __shared__ int   si[KSEL];
    if (tid < KSEL) {
        sv[tid] = g_vals[row * KSEL + tid];
        si[tid] = g_idx [row * KSEL + tid];
    }
    __syncthreads();
    if (tid >= 250) return;
    const int c = tid * 4;
    float4 acc = *(const float4*)&bc[c];
#pragma unroll 4
    for (int j = 0; j < KSEL; j++) {
        const float v = sv[j];
        const float4 w = *(const float4*)&Wc[(size_t)si[j] * CDIM + c];
        acc.x = fmaf(v, w.x, acc.x);
        acc.y = fmaf(v, w.y, acc.y);
        acc.z = fmaf(v, w.z, acc.z);
        acc.w = fmaf(v, w.w, acc.w);
    }
    *(float4*)&logits[(size_t)row * CDIM + c] = acc;
}

// ----------------------------------------------------------------------------------------
extern "C" void kernel_launch(void* const* d_in, const int* in_sizes, int n_in,
                              void* d_out, int out_size)
{
    const float* x  = (const float*)d_in[0];
    const float* Wi = (const float*)d_in[1];
    const float* bi = (const float*)d_in[2];
    const float* Wc = (const float*)d_in[3];
    const float* bc = (const float*)d_in[4];
    (void)in_sizes; (void)n_in; (void)out_size;

    float* sparse = (float*)d_out;
    float* logits = (float*)d_out + (size_t)BDIM * FDIM;

    static int smem_set = 0;
    if (!smem_set) {
        cudaFuncSetAttribute(mma_gemm, cudaFuncAttributeMaxDynamicSharedMemorySize, SMEMDYN);
        smem_set = 1;
    }

    split_A<<<2048, 256>>>(x);
    split_BT<<<dim3(FDIM / 32, DDIM / 32), 256>>>(Wi);
    mma_gemm<<<dim3(FDIM / 128, BDIM / 128), 256, SMEMDYN>>>(bi);
    topk_kernel<<<BDIM, 256>>>(sparse);
    repair_kernel<<<MAXFLAG, 256>>>(x, Wi, bi, sparse);
    cls_kernel<<<BDIM, 256>>>(Wc, bc, logits);
}

// round 7
// speedup vs baseline: 2.4623x; 1.0136x over previous
#include <cuda_runtime.h>
#include <cuda_bf16.h>
#include <cstdint>

#define BDIM 4096
#define DDIM 768
#define FDIM 6144
#define CDIM 1000
#define KSEL 64

// ---- mma-GEMM tiling --------------------------------------------------------
#define KC2 32
#define NCH (DDIM / KC2)          // 24
#define ROWBYTES 80               // 32 bf16 (64B) + 16B pad: conflict-free ldmatrix
#define TILEB (128 * ROWBYTES)    // 10240 B
#define BUFB (4 * TILEB)          // Ah, Am, Bh, Bm
#define SMEMDYN (2 * BUFB)        // 81920 B

#define MAXFLAG 4096
#define CAND_MAX 64
#define GAP_TAU 3e-4f

// ---- scratch ------------------------------------------------------------------
__device__ float g_h[(size_t)BDIM * FDIM];
__device__ float g_vals[BDIM * KSEL];
__device__ int   g_idx [BDIM * KSEL];
__device__ unsigned g_T[BDIM];
__device__ unsigned g_nflag;
__device__ int   g_flagrows[MAXFLAG];
__device__ __nv_bfloat16 gAh[(size_t)BDIM * DDIM];
__device__ __nv_bfloat16 gAm[(size_t)BDIM * DDIM];
__device__ __nv_bfloat16 gBh[(size_t)FDIM * DDIM];   // W_inter^T limbs, [n][k]
__device__ __nv_bfloat16 gBm[(size_t)FDIM * DDIM];

// ---- helpers -------------------------------------------------------------------
__device__ __forceinline__ uint32_t smem_u32(const void* p) {
    uint32_t a;
    asm("{ .reg .u64 t; cvta.to.shared.u64 t, %1; cvt.u32.u64 %0, t; }" : "=r"(a) : "l"(p));
    return a;
}
__device__ __forceinline__ void cp_async16(uint32_t dst, const void* src) {
    asm volatile("cp.async.cg.shared.global [%0], [%1], 16;" :: "r"(dst), "l"(src));
}
__device__ __forceinline__ void ldsm4(uint32_t* r, uint32_t addr) {
    asm volatile("ldmatrix.sync.aligned.m8n8.x4.shared.b16 {%0,%1,%2,%3}, [%4];"
                 : "=r"(r[0]), "=r"(r[1]), "=r"(r[2]), "=r"(r[3]) : "r"(addr));
}
__device__ __forceinline__ void mma16816(float* d, const uint32_t* a, const uint32_t* b) {
    asm volatile("mma.sync.aligned.m16n8k16.row.col.f32.bf16.bf16.f32 "
                 "{%0,%1,%2,%3}, {%4,%5,%6,%7}, {%8,%9}, {%0,%1,%2,%3};"
                 : "+f"(d[0]), "+f"(d[1]), "+f"(d[2]), "+f"(d[3])
                 : "r"(a[0]), "r"(a[1]), "r"(a[2]), "r"(a[3]), "r"(b[0]), "r"(b[1]));
}

// ---- split kernels: exact 2-limb bf16 decomposition -----------------------------
__global__ void split_A(const float* __restrict__ x)
{
    if (blockIdx.x == 0 && threadIdx.x == 0) g_nflag = 0;
    const size_t n = (size_t)BDIM * DDIM;
    for (size_t i = (size_t)blockIdx.x * blockDim.x + threadIdx.x; i < n;
         i += (size_t)gridDim.x * blockDim.x) {
        float v = x[i];
        __nv_bfloat16 h = __float2bfloat16_rn(v);
        float r1 = v - __bfloat162float(h);
        gAh[i] = h; gAm[i] = __float2bfloat16_rn(r1);
    }
}

__global__ void __launch_bounds__(256) split_BT(const float* __restrict__ W)
{
    __shared__ float t[32][33];
    const int n0 = blockIdx.x * 32, k0 = blockIdx.y * 32;
    const int tx = threadIdx.x & 31, ty = threadIdx.x >> 5;
#pragma unroll
    for (int i = 0; i < 32; i += 8)
        t[ty + i][tx] = W[(size_t)(k0 + ty + i) * FDIM + n0 + tx];
    __syncthreads();
#pragma unroll
    for (int i = 0; i < 32; i += 8) {
        float v = t[tx][ty + i];
        __nv_bfloat16 h = __float2bfloat16_rn(v);
        float r1 = v - __bfloat162float(h);
        size_t o = (size_t)(n0 + ty + i) * DDIM + k0 + tx;
        gBh[o] = h; gBm[o] = __float2bfloat16_rn(r1);
    }
}

// ---- tensor-core GEMM: h = relu(x @ W + b), bf16x3 -------------------------------
__device__ __forceinline__ void load_tiles(uint32_t sbase, int buf, int ch,
                                           int bm, int bn, int tid)
{
    const uint32_t bb = sbase + buf * BUFB;
    const int k0 = ch * KC2;
    const __nv_bfloat16* srcs[4] = { gAh, gAm, gBh, gBm };
#pragma unroll
    for (int t = 0; t < 4; t++) {
        const int rbase = (t < 2) ? bm : bn;
        const __nv_bfloat16* sp = srcs[t] + (size_t)rbase * DDIM + k0;
        const uint32_t tb = bb + t * TILEB;
#pragma unroll
        for (int i = tid; i < 512; i += 256) {
            const int row = i >> 2, seg = i & 3;
            cp_async16(tb + row * ROWBYTES + seg * 16, sp + (size_t)row * DDIM + seg * 8);
        }
    }
    asm volatile("cp.async.commit_group;" ::: "memory");
}

__global__ void __launch_bounds__(256, 1) mma_gemm(const float* __restrict__ bias)
{
    extern __shared__ char dsm[];
    const uint32_t sbase = smem_u32(dsm);
    const int tid = threadIdx.x, wid = tid >> 5, lane = tid & 31;
    const int bm = blockIdx.y * 128, bn = blockIdx.x * 128;
    const int wm = (wid >> 2) * 64;   // 0 / 64
    const int wn = (wid & 3) * 32;    // 0..96

    float d[4][4][4];
#pragma unroll
    for (int i = 0; i < 4; i++)
#pragma unroll
        for (int j = 0; j < 4; j++)
#pragma unroll
            for (int q = 0; q < 4; q++) d[i][j][q] = 0.f;

    load_tiles(sbase, 0, 0, bm, bn, tid);
    load_tiles(sbase, 1, 1, bm, bn, tid);

    const uint32_t aoff = (uint32_t)(wm + (lane & 15)) * ROWBYTES + ((lane >> 4) * 8) * 2;
    const uint32_t boff = (uint32_t)(wn + ((lane >> 4) & 1) * 8 + (lane & 7)) * ROWBYTES
                        + (((lane >> 3) & 1) * 8) * 2;

#pragma unroll 1
    for (int ch = 0; ch < NCH; ch++) {
        const int buf = ch & 1;
        if (ch < NCH - 1) asm volatile("cp.async.wait_group 1;" ::: "memory");
        else              asm volatile("cp.async.wait_group 0;" ::: "memory");
        __syncthreads();

        const uint32_t bb = sbase + buf * BUFB;
#pragma unroll
        for (int kk = 0; kk < 2; kk++) {
            const uint32_t ko = kk * 32;
            uint32_t ah[4][4], am[4][4], bh[2][4], bmm[2][4];
#pragma unroll
            for (int ma = 0; ma < 4; ma++) {
                ldsm4(ah[ma], bb + 0 * TILEB + aoff + ma * 16 * ROWBYTES + ko);
                ldsm4(am[ma], bb + 1 * TILEB + aoff + ma * 16 * ROWBYTES + ko);
            }
#pragma unroll
            for (int pr = 0; pr < 2; pr++) {
                ldsm4(bh[pr],  bb + 2 * TILEB + boff + pr * 16 * ROWBYTES + ko);
                ldsm4(bmm[pr], bb + 3 * TILEB + boff + pr * 16 * ROWBYTES + ko);
            }
#pragma unroll
            for (int ma = 0; ma < 4; ma++)
#pragma unroll
                for (int na = 0; na < 4; na++) {
                    const uint32_t* bhf = &bh[na >> 1][(na & 1) * 2];
                    const uint32_t* bmf = &bmm[na >> 1][(na & 1) * 2];
                    mma16816(d[ma][na], ah[ma], bhf);   // h*h
                    mma16816(d[ma][na], ah[ma], bmf);   // h*m
                    mma16816(d[ma][na], am[ma], bhf);   // m*h
                }
        }
        __syncthreads();
        if (ch + 2 < NCH) load_tiles(sbase, buf, ch + 2, bm, bn, tid);
    }

#pragma unroll
    for (int na = 0; na < 4; na++) {
        const int n0g = bn + wn + na * 8 + (lane & 3) * 2;
        const float b0 = bias[n0g], b1 = bias[n0g + 1];
#pragma unroll
        for (int ma = 0; ma < 4; ma++) {
            const int m0g = bm + wm + ma * 16 + (lane >> 2);
            float v0 = __fadd_rn(d[ma][na][0], b0);
            float v1 = __fadd_rn(d[ma][na][1], b1);
            float v2 = __fadd_rn(d[ma][na][2], b0);
            float v3 = __fadd_rn(d[ma][na][3], b1);
            float2 o0 = { (v0 > 0.f) ? v0 : 0.f, (v1 > 0.f) ? v1 : 0.f };
            float2 o1 = { (v2 > 0.f) ? v2 : 0.f, (v3 > 0.f) ? v3 : 0.f };
            *(float2*)&g_h[(size_t)m0g * FDIM + n0g]       = o0;
            *(float2*)&g_h[(size_t)(m0g + 8) * FDIM + n0g] = o1;
        }
    }
}

// ---- top-64: register-resident bitwise binary-search select ----------------------
// Each thread holds 24 values (6 x uint4). Exact threshold T (bits of 64th
// largest) built greedily from bit 30 down via block counts (atomic-free).
// Ties at T taken in ascending index order (lax.top_k stability). Rows with
// boundary gap < GAP_TAU (or tie spill) flagged for exact repair.
__global__ void __launch_bounds__(256) topk_kernel(float* __restrict__ sparse)
{
    const int row = blockIdx.x;
    const int tid = threadIdx.x;
    const int lane = tid & 31, wid = tid >> 5;

    __shared__ unsigned warpcnt[2][8];
    __shared__ unsigned warpmax[8];
    __shared__ unsigned s_cnt, s_eqcnt;
    __shared__ unsigned eq_idx[64];

    const float* hrow = g_h + (size_t)row * FDIM;
    uint4 vb[6];
#pragma unroll
    for (int q = 0; q < 6; q++)
        vb[q] = ((const uint4*)hrow)[q * 256 + tid];   // cols q*1024 + tid*4 + {0..3}

    if (tid == 0) { s_cnt = 0; s_eqcnt = 0; }

    // ---- greedy bitwise search for T = bits of the 64th-largest value
    unsigned T = 0;
#pragma unroll 1
    for (int b = 30; b >= 0; --b) {
        const unsigned cand = T | (1u << b);
        unsigned lc = 0;
#pragma unroll
        for (int q = 0; q < 6; q++) {
            lc += (vb[q].x >= cand) + (vb[q].y >= cand)
                + (vb[q].z >= cand) + (vb[q].w >= cand);
        }
        lc = __reduce_add_sync(0xFFFFFFFFu, lc);
        const int pb = b & 1;
        if (lane == 0) warpcnt[pb][wid] = lc;
        __syncthreads();
        unsigned cnt = 0;
#pragma unroll
        for (int w = 0; w < 8; w++) cnt += warpcnt[pb][w];
        if (cnt >= KSEL) T = cand;
    }
    __syncthreads();

    const float Tval = __uint_as_float(T);
    float* srow = sparse + (size_t)row * FDIM;
    float* vrow = g_vals + row * KSEL;
    int*   irow = g_idx  + row * KSEL;

    // ---- classify elements, write sparse (eq handled in tail), collect selected
    unsigned bmax = 0;
#pragma unroll
    for (int q = 0; q < 6; q++) {
        const int c0 = q * 1024 + tid * 4;
        unsigned u[4] = { vb[q].x, vb[q].y, vb[q].z, vb[q].w };
        float o[4];
#pragma unroll
        for (int c = 0; c < 4; c++) {
            o[c] = 0.f;
            if (u[c] > T) {
                o[c] = __uint_as_float(u[c]);
                unsigned slot = atomicAdd(&s_cnt, 1u);
                vrow[slot] = o[c];
                irow[slot] = c0 + c;
            } else if (u[c] == T) {
                unsigned e = atomicAdd(&s_eqcnt, 1u);
                if (e < 64u) eq_idx[e] = (unsigned)(c0 + c);
            } else {
                bmax = max(bmax, u[c]);
            }
        }
        *(float4*)&srow[c0] = *(const float4*)o;
    }
#pragma unroll
    for (int o2 = 16; o2; o2 >>= 1) bmax = max(bmax, __shfl_xor_sync(0xFFFFFFFFu, bmax, o2));
    if (lane == 0) warpmax[wid] = bmax;
    __syncthreads();

    if (tid == 0) {
        unsigned below = 0;
#pragma unroll
        for (int w = 0; w < 8; w++) below = max(below, warpmax[w]);

        const unsigned n_gt = s_cnt;            // count(v > T) < 64
        const unsigned need = KSEL - n_gt;
        unsigned ne = min(s_eqcnt, 64u);
        for (unsigned a = 1; a < ne; a++) {     // ascending index (tiny)
            unsigned key = eq_idx[a];
            int b = (int)a - 1;
            while (b >= 0 && eq_idx[b] > key) { eq_idx[b + 1] = eq_idx[b]; b--; }
            eq_idx[b + 1] = key;
        }
        for (unsigned a = 0; a < need; a++) {
            if (a < ne) {
                unsigned fi = eq_idx[a];
                srow[fi] = Tval;
                vrow[n_gt + a] = Tval;
                irow[n_gt + a] = (int)fi;
            } else {
                vrow[n_gt + a] = 0.f;           // only when T == 0
                irow[n_gt + a] = 0;
            }
        }
        g_T[row] = T;
        bool spill = (s_eqcnt > need);
        if (T != 0u && (spill || (Tval - __uint_as_float(below)) < GAP_TAU)) {
            unsigned p = atomicAdd(&g_nflag, 1u);
            if (p < MAXFLAG) g_flagrows[p] = row;
        }
    }
}

// ---- exact repair of flagged rows -------------------------------------------------
__global__ void __launch_bounds__(256) repair_kernel(
    const float* __restrict__ x, const float* __restrict__ Wi,
    const float* __restrict__ bi, float* __restrict__ sparse)
{
    __shared__ float xs[DDIM];
    __shared__ int   cand[CAND_MAX];
    __shared__ float cex[CAND_MAX];
    __shared__ float red[256];
    __shared__ unsigned s_nc, s_nhi;

    unsigned nf = min(g_nflag, (unsigned)MAXFLAG);
    if (blockIdx.x >= nf) return;
    const int row = g_flagrows[blockIdx.x];
    const int tid = threadIdx.x;
    const float Tval = __uint_as_float(g_T[row]);
    const float* hrow = g_h + (size_t)row * FDIM;

    for (int i = tid; i < DDIM; i += 256) xs[i] = x[(size_t)row * DDIM + i];
    if (tid == 0) { s_nc = 0; s_nhi = 0; }
    __syncthreads();

    unsigned nhi_loc = 0;
    for (int f = tid; f < FDIM; f += 256) {
        float v = hrow[f];
        if (fabsf(v - Tval) <= GAP_TAU) {
            unsigned p = atomicAdd(&s_nc, 1u);
            if (p < CAND_MAX) cand[p] = f;
        } else if (v > Tval) nhi_loc++;
    }
    atomicAdd(&s_nhi, nhi_loc);
    __syncthreads();
    const unsigned nc = s_nc;
    if (nc > CAND_MAX) return;

    for (unsigned j = 0; j < nc; j++) {
        const int f = cand[j];
        float s = 0.f, c = 0.f;
        for (int d = tid; d < DDIM; d += 256) {
            float p = __fmaf_rn(xs[d], Wi[(size_t)d * FDIM + f], 0.f);
            float y = __fsub_rn(p, c);
            float t2 = __fadd_rn(s, y);
            c = __fsub_rn(__fsub_rn(t2, s), y);
            s = t2;
        }
        red[tid] = s;
        __syncthreads();
        for (int o = 128; o > 0; o >>= 1) {
            if (tid < o) red[tid] = __fadd_rn(red[tid], red[tid + o]);
            __syncthreads();
        }
        if (tid == 0) {
            float v = __fadd_rn(red[0], bi[f]);
            cex[j] = (v > 0.f) ? v : 0.f;
        }
        __syncthreads();
    }
    if (tid != 0) return;

    float* srow = sparse + (size_t)row * FDIM;
    float* vrow = g_vals + row * KSEL;
    int*   irow = g_idx  + row * KSEL;

    int k_rem = KSEL - (int)s_nhi;
    bool want[CAND_MAX], cur[CAND_MAX];
    for (unsigned j = 0; j < nc; j++) {
        want[j] = false;
        cur[j] = (srow[cand[j]] != 0.f);
    }
    for (int slot = 0; slot < k_rem; slot++) {
        int best = -1;
        for (unsigned j = 0; j < nc; j++) {
            if (want[j]) continue;
            if (best < 0 || cex[j] > cex[best] ||
                (cex[j] == cex[best] && cand[j] < cand[best])) best = (int)j;
        }
        if (best >= 0) want[best] = true;
    }
    int addq[CAND_MAX]; int na = 0;
    for (unsigned j = 0; j < nc; j++) if (want[j] && !cur[j]) addq[na++] = (int)j;
    int ai = 0;
    for (unsigned j = 0; j < nc && ai < na; j++) {
        if (cur[j] && !want[j]) {
            int rf = cand[j];
            int af = cand[addq[ai]]; ai++;
            float av = hrow[af];
            srow[rf] = 0.f;
            srow[af] = av;
            for (int q = 0; q < KSEL; q++)
                if (irow[q] == rf) { irow[q] = af; vrow[q] = av; break; }
        }
    }
}

// ---- classifier ---------------------------------------------------------------------
__global__ void __launch_bounds__(256) cls_kernel(
    const float* __restrict__ Wc, const float* __restrict__ bc,
    float* __restrict__ logits)
{
    const int row = blockIdx.x;
    const int tid = threadIdx.x;
    __shared__ float sv[KSEL];
    __shared__ int   si[KSEL];
    if (tid < KSEL) {
        sv[tid] = g_vals[row * KSEL + tid];
        si[tid] = g_idx [row * KSEL + tid];
    }
    __syncthreads();
    if (tid >= 250) return;
    const int c = tid * 4;
    float4 acc = *(const float4*)&bc[c];
#pragma unroll 4
    for (int j = 0; j < KSEL; j++) {
        const float v = sv[j];
        const float4 w = *(const float4*)&Wc[(size_t)si[j] * CDIM + c];
        acc.x = fmaf(v, w.x, acc.x);
        acc.y = fmaf(v, w.y, acc.y);
        acc.z = fmaf(v, w.z, acc.z);
        acc.w = fmaf(v, w.w, acc.w);
    }
    *(float4*)&logits[(size_t)row * CDIM + c] = acc;
}

// ----------------------------------------------------------------------------------------
extern "C" void kernel_launch(void* const* d_in, const int* in_sizes, int n_in,
                              void* d_out, int out_size)
{
    const float* x  = (const float*)d_in[0];
    const float* Wi = (const float*)d_in[1];
    const float* bi = (const float*)d_in[2];
    const float* Wc = (const float*)d_in[3];
    const float* bc = (const float*)d_in[4];
    (void)in_sizes; (void)n_in; (void)out_size;

    float* sparse = (float*)d_out;
    float* logits = (float*)d_out + (size_t)BDIM * FDIM;

    static int smem_set = 0;
    if (!smem_set) {
        cudaFuncSetAttribute(mma_gemm, cudaFuncAttributeMaxDynamicSharedMemorySize, SMEMDYN);
        smem_set = 1;
    }

    split_A<<<2048, 256>>>(x);
    split_BT<<<dim3(FDIM / 32, DDIM / 32), 256>>>(Wi);
    mma_gemm<<<dim3(FDIM / 128, BDIM / 128), 256, SMEMDYN>>>(bi);
    topk_kernel<<<BDIM, 256>>>(sparse);
    repair_kernel<<<MAXFLAG, 256>>>(x, Wi, bi, sparse);
    cls_kernel<<<BDIM, 256>>>(Wc, bc, logits);
}

// round 8
// speedup vs baseline: 2.5198x; 1.0233x over previous
#include <cuda_runtime.h>
#include <cuda_bf16.h>
#include <cstdint>

#define BDIM 4096
#define DDIM 768
#define FDIM 6144
#define CDIM 1000
#define KSEL 64

// ---- mma-GEMM tiling --------------------------------------------------------
#define KC2 32
#define NCH (DDIM / KC2)          // 24
#define ROWBYTES 80               // 32 bf16 (64B) + 16B pad: conflict-free ldmatrix
#define TILEB (128 * ROWBYTES)    // 10240 B
#define BUFB (4 * TILEB)          // Ah, Am, Bh, Bm
#define SMEMDYN (2 * BUFB)        // 81920 B

#define MAXFLAG 4096
#define CAND_MAX 64
#define GAP_TAU 3e-4f

// top-k candidate machinery
#define CANDN 256
#define BREAK_CNT 160

// ---- scratch ------------------------------------------------------------------
__device__ float g_h[(size_t)BDIM * FDIM];
__device__ float g_vals[BDIM * KSEL];
__device__ int   g_idx [BDIM * KSEL];
__device__ unsigned g_T[BDIM];
__device__ unsigned g_nflag;
__device__ int   g_flagrows[MAXFLAG];
__device__ __nv_bfloat16 gAh[(size_t)BDIM * DDIM];
__device__ __nv_bfloat16 gAm[(size_t)BDIM * DDIM];
__device__ __nv_bfloat16 gBh[(size_t)FDIM * DDIM];   // W_inter^T limbs, [n][k]
__device__ __nv_bfloat16 gBm[(size_t)FDIM * DDIM];

// ---- helpers -------------------------------------------------------------------
__device__ __forceinline__ uint32_t smem_u32(const void* p) {
    uint32_t a;
    asm("{ .reg .u64 t; cvta.to.shared.u64 t, %1; cvt.u32.u64 %0, t; }" : "=r"(a) : "l"(p));
    return a;
}
__device__ __forceinline__ void cp_async16(uint32_t dst, const void* src) {
    asm volatile("cp.async.cg.shared.global [%0], [%1], 16;" :: "r"(dst), "l"(src));
}
__device__ __forceinline__ void ldsm4(uint32_t* r, uint32_t addr) {
    asm volatile("ldmatrix.sync.aligned.m8n8.x4.shared.b16 {%0,%1,%2,%3}, [%4];"
                 : "=r"(r[0]), "=r"(r[1]), "=r"(r[2]), "=r"(r[3]) : "r"(addr));
}
__device__ __forceinline__ void mma16816(float* d, const uint32_t* a, const uint32_t* b) {
    asm volatile("mma.sync.aligned.m16n8k16.row.col.f32.bf16.bf16.f32 "
                 "{%0,%1,%2,%3}, {%4,%5,%6,%7}, {%8,%9}, {%0,%1,%2,%3};"
                 : "+f"(d[0]), "+f"(d[1]), "+f"(d[2]), "+f"(d[3])
                 : "r"(a[0]), "r"(a[1]), "r"(a[2]), "r"(a[3]), "r"(b[0]), "r"(b[1]));
}

// ---- split kernels: exact 2-limb bf16 decomposition -----------------------------
__global__ void split_A(const float* __restrict__ x)
{
    if (blockIdx.x == 0 && threadIdx.x == 0) g_nflag = 0;
    const size_t n = (size_t)BDIM * DDIM;
    for (size_t i = (size_t)blockIdx.x * blockDim.x + threadIdx.x; i < n;
         i += (size_t)gridDim.x * blockDim.x) {
        float v = x[i];
        __nv_bfloat16 h = __float2bfloat16_rn(v);
        float r1 = v - __bfloat162float(h);
        gAh[i] = h; gAm[i] = __float2bfloat16_rn(r1);
    }
}

__global__ void __launch_bounds__(256) split_BT(const float* __restrict__ W)
{
    __shared__ float t[32][33];
    const int n0 = blockIdx.x * 32, k0 = blockIdx.y * 32;
    const int tx = threadIdx.x & 31, ty = threadIdx.x >> 5;
#pragma unroll
    for (int i = 0; i < 32; i += 8)
        t[ty + i][tx] = W[(size_t)(k0 + ty + i) * FDIM + n0 + tx];
    __syncthreads();
#pragma unroll
    for (int i = 0; i < 32; i += 8) {
        float v = t[tx][ty + i];
        __nv_bfloat16 h = __float2bfloat16_rn(v);
        float r1 = v - __bfloat162float(h);
        size_t o = (size_t)(n0 + ty + i) * DDIM + k0 + tx;
        gBh[o] = h; gBm[o] = __float2bfloat16_rn(r1);
    }
}

// ---- tensor-core GEMM: h = relu(x @ W + b), bf16x3 -------------------------------
__device__ __forceinline__ void load_tiles(uint32_t sbase, int buf, int ch,
                                           int bm, int bn, int tid)
{
    const uint32_t bb = sbase + buf * BUFB;
    const int k0 = ch * KC2;
    const __nv_bfloat16* srcs[4] = { gAh, gAm, gBh, gBm };
#pragma unroll
    for (int t = 0; t < 4; t++) {
        const int rbase = (t < 2) ? bm : bn;
        const __nv_bfloat16* sp = srcs[t] + (size_t)rbase * DDIM + k0;
        const uint32_t tb = bb + t * TILEB;
#pragma unroll
        for (int i = tid; i < 512; i += 256) {
            const int row = i >> 2, seg = i & 3;
            cp_async16(tb + row * ROWBYTES + seg * 16, sp + (size_t)row * DDIM + seg * 8);
        }
    }
    asm volatile("cp.async.commit_group;" ::: "memory");
}

__global__ void __launch_bounds__(256, 1) mma_gemm(const float* __restrict__ bias)
{
    extern __shared__ char dsm[];
    const uint32_t sbase = smem_u32(dsm);
    const int tid = threadIdx.x, wid = tid >> 5, lane = tid & 31;
    const int bm = blockIdx.y * 128, bn = blockIdx.x * 128;
    const int wm = (wid >> 2) * 64;
    const int wn = (wid & 3) * 32;

    float d[4][4][4];
#pragma unroll
    for (int i = 0; i < 4; i++)
#pragma unroll
        for (int j = 0; j < 4; j++)
#pragma unroll
            for (int q = 0; q < 4; q++) d[i][j][q] = 0.f;

    load_tiles(sbase, 0, 0, bm, bn, tid);
    load_tiles(sbase, 1, 1, bm, bn, tid);

    const uint32_t aoff = (uint32_t)(wm + (lane & 15)) * ROWBYTES + ((lane >> 4) * 8) * 2;
    const uint32_t boff = (uint32_t)(wn + ((lane >> 4) & 1) * 8 + (lane & 7)) * ROWBYTES
                        + (((lane >> 3) & 1) * 8) * 2;

#pragma unroll 1
    for (int ch = 0; ch < NCH; ch++) {
        const int buf = ch & 1;
        if (ch < NCH - 1) asm volatile("cp.async.wait_group 1;" ::: "memory");
        else              asm volatile("cp.async.wait_group 0;" ::: "memory");
        __syncthreads();

        const uint32_t bb = sbase + buf * BUFB;
#pragma unroll
        for (int kk = 0; kk < 2; kk++) {
            const uint32_t ko = kk * 32;
            uint32_t ah[4][4], am[4][4], bh[2][4], bmm[2][4];
#pragma unroll
            for (int ma = 0; ma < 4; ma++) {
                ldsm4(ah[ma], bb + 0 * TILEB + aoff + ma * 16 * ROWBYTES + ko);
                ldsm4(am[ma], bb + 1 * TILEB + aoff + ma * 16 * ROWBYTES + ko);
            }
#pragma unroll
            for (int pr = 0; pr < 2; pr++) {
                ldsm4(bh[pr],  bb + 2 * TILEB + boff + pr * 16 * ROWBYTES + ko);
                ldsm4(bmm[pr], bb + 3 * TILEB + boff + pr * 16 * ROWBYTES + ko);
            }
#pragma unroll
            for (int ma = 0; ma < 4; ma++)
#pragma unroll
                for (int na = 0; na < 4; na++) {
                    const uint32_t* bhf = &bh[na >> 1][(na & 1) * 2];
                    const uint32_t* bmf = &bmm[na >> 1][(na & 1) * 2];
                    mma16816(d[ma][na], ah[ma], bhf);
                    mma16816(d[ma][na], ah[ma], bmf);
                    mma16816(d[ma][na], am[ma], bhf);
                }
        }
        __syncthreads();
        if (ch + 2 < NCH) load_tiles(sbase, buf, ch + 2, bm, bn, tid);
    }

#pragma unroll
    for (int na = 0; na < 4; na++) {
        const int n0g = bn + wn + na * 8 + (lane & 3) * 2;
        const float b0 = bias[n0g], b1 = bias[n0g + 1];
#pragma unroll
        for (int ma = 0; ma < 4; ma++) {
            const int m0g = bm + wm + ma * 16 + (lane >> 2);
            float v0 = __fadd_rn(d[ma][na][0], b0);
            float v1 = __fadd_rn(d[ma][na][1], b1);
            float v2 = __fadd_rn(d[ma][na][2], b0);
            float v3 = __fadd_rn(d[ma][na][3], b1);
            float2 o0 = { (v0 > 0.f) ? v0 : 0.f, (v1 > 0.f) ? v1 : 0.f };
            float2 o1 = { (v2 > 0.f) ? v2 : 0.f, (v3 > 0.f) ? v3 : 0.f };
            *(float2*)&g_h[(size_t)m0g * FDIM + n0g]       = o0;
            *(float2*)&g_h[(size_t)(m0g + 8) * FDIM + n0g] = o1;
        }
    }
}

// ---- top-64: truncated bitwise search + exact candidate ranking -------------------
// Phase 1: greedy MSB-first threshold search, stopping once count(v >= T) <= BREAK_CNT
//          (exact invariant: T <= v64-bits, candidate set {v >= T} contains top-64).
// Phase 2: ballot-compact candidates (value,index) into smem (atomic-free).
// Phase 3: exact rank by (value desc, index asc) over <=BREAK_CNT candidates =
//          lax.top_k selection; rank 63/64 give the 64th/65th values (exact gap).
// Phase 4: write sparse (cmp vs v64), patch ties, write vals/idx sorted by rank.
__global__ void __launch_bounds__(256) topk_kernel(float* __restrict__ sparse)
{
    const int row = blockIdx.x;
    const int tid = threadIdx.x;
    const int lane = tid & 31, wid = tid >> 5;

    __shared__ unsigned warpcnt[2][8];
    __shared__ unsigned warpmax[8];
    __shared__ unsigned cu[CANDN];
    __shared__ int      ci[CANDN];
    __shared__ unsigned s_T64, s_v65;

    const float* hrow = g_h + (size_t)row * FDIM;
    uint4 vb[6];
#pragma unroll
    for (int q = 0; q < 6; q++)
        vb[q] = ((const uint4*)hrow)[q * 256 + tid];   // cols q*1024 + tid*4 + {0..3}

    if (tid == 0) { s_T64 = 0u; s_v65 = 0u; }

    // ---- phase 1: truncated greedy bit search
    unsigned T = 0, curcnt = FDIM;
#pragma unroll 1
    for (int b = 30; b >= 0; --b) {
        const unsigned cand = T | (1u << b);
        unsigned lc = 0;
#pragma unroll
        for (int q = 0; q < 6; q++) {
            lc += (vb[q].x >= cand) + (vb[q].y >= cand)
                + (vb[q].z >= cand) + (vb[q].w >= cand);
        }
        lc = __reduce_add_sync(0xFFFFFFFFu, lc);
        const int pb = b & 1;
        if (lane == 0) warpcnt[pb][wid] = lc;
        __syncthreads();
        unsigned cnt = 0;
#pragma unroll
        for (int w = 0; w < 8; w++) cnt += warpcnt[pb][w];
        if (cnt >= KSEL) { T = cand; curcnt = cnt; }
        if (curcnt <= BREAK_CNT) break;
    }
    __syncthreads();

    // ---- phase 2: atomic-free ballot compaction of candidates {u >= T}
    unsigned wcnt = 0;
#pragma unroll
    for (int q = 0; q < 6; q++) {
        unsigned u[4] = { vb[q].x, vb[q].y, vb[q].z, vb[q].w };
#pragma unroll
        for (int c = 0; c < 4; c++)
            wcnt += __popc(__ballot_sync(0xFFFFFFFFu, u[c] >= T));
    }
    if (lane == 0) warpcnt[0][wid] = wcnt;
    __syncthreads();
    unsigned nc = 0, wbase = 0;
#pragma unroll
    for (int w = 0; w < 8; w++) {
        if (w < wid) wbase += warpcnt[0][w];
        nc += warpcnt[0][w];
    }
    if (nc > CANDN) nc = CANDN;   // statistically impossible overflow guard
    {
        unsigned base = wbase;
        const unsigned ltmask = (1u << lane) - 1u;
#pragma unroll
        for (int q = 0; q < 6; q++) {
            const int c0 = q * 1024 + tid * 4;
            unsigned u[4] = { vb[q].x, vb[q].y, vb[q].z, vb[q].w };
#pragma unroll
            for (int c = 0; c < 4; c++) {
                const bool pred = (u[c] >= T);
                const unsigned m = __ballot_sync(0xFFFFFFFFu, pred);
                if (pred) {
                    unsigned slot = base + __popc(m & ltmask);
                    if (slot < CANDN) { cu[slot] = u[c]; ci[slot] = c0 + c; }
                }
                base += __popc(m);
            }
        }
    }
    __syncthreads();

    // ---- phase 3: exact rank (value desc, index asc) over candidates
    float* vrow = g_vals + row * KSEL;
    int*   irow = g_idx  + row * KSEL;
    for (unsigned j = tid; j < nc; j += 256) {
        const unsigned v = cu[j];
        const int id = ci[j];
        int r = 0;
        for (unsigned m = 0; m < nc; m++) {
            const unsigned w = cu[m];
            r += (w > v) || (w == v && ci[m] < id);
        }
        if (r < KSEL) { vrow[r] = __uint_as_float(v); irow[r] = id; }
        if (r == KSEL - 1) s_T64 = v;
        if (r == KSEL)     s_v65 = v;
    }
    __syncthreads();
    const unsigned T64 = s_T64;

    // ---- phase 4: write sparse, track non-candidate max (needed when nc == 64)
    float* srow = sparse + (size_t)row * FDIM;
    unsigned bmax = 0;
#pragma unroll
    for (int q = 0; q < 6; q++) {
        const int c0 = q * 1024 + tid * 4;
        unsigned u[4] = { vb[q].x, vb[q].y, vb[q].z, vb[q].w };
        float o[4];
#pragma unroll
        for (int c = 0; c < 4; c++) {
            o[c] = (u[c] > T64) ? __uint_as_float(u[c]) : 0.f;
            if (u[c] < T) bmax = max(bmax, u[c]);
        }
        *(float4*)&srow[c0] = *(const float4*)o;
    }
#pragma unroll
    for (int o2 = 16; o2; o2 >>= 1) bmax = max(bmax, __shfl_xor_sync(0xFFFFFFFFu, bmax, o2));
    if (lane == 0) warpmax[wid] = bmax;
    __syncthreads();

    // patch ties at the 64th value (rank phase selected them; classify wrote 0)
    if (tid < KSEL) srow[irow[tid]] = vrow[tid];

    if (tid == 0) {
        unsigned below;
        if (nc > KSEL) below = s_v65;
        else {
            below = 0;
#pragma unroll
            for (int w = 0; w < 8; w++) below = max(below, warpmax[w]);
        }
        g_T[row] = T64;
        const float gap = __uint_as_float(T64) - __uint_as_float(below);
        if (T64 != 0u && gap < GAP_TAU) {
            unsigned p = atomicAdd(&g_nflag, 1u);
            if (p < MAXFLAG) g_flagrows[p] = row;
        }
    }
}

// ---- exact repair of flagged rows -------------------------------------------------
__global__ void __launch_bounds__(256) repair_kernel(
    const float* __restrict__ x, const float* __restrict__ Wi,
    const float* __restrict__ bi, float* __restrict__ sparse)
{
    __shared__ float xs[DDIM];
    __shared__ int   cand[CAND_MAX];
    __shared__ float cex[CAND_MAX];
    __shared__ float red[256];
    __shared__ unsigned s_nc, s_nhi;

    unsigned nf = min(g_nflag, (unsigned)MAXFLAG);
    if (blockIdx.x >= nf) return;
    const int row = g_flagrows[blockIdx.x];
    const int tid = threadIdx.x;
    const float Tval = __uint_as_float(g_T[row]);
    const float* hrow = g_h + (size_t)row * FDIM;

    for (int i = tid; i < DDIM; i += 256) xs[i] = x[(size_t)row * DDIM + i];
    if (tid == 0) { s_nc = 0; s_nhi = 0; }
    __syncthreads();

    unsigned nhi_loc = 0;
    for (int f = tid; f < FDIM; f += 256) {
        float v = hrow[f];
        if (fabsf(v - Tval) <= GAP_TAU) {
            unsigned p = atomicAdd(&s_nc, 1u);
            if (p < CAND_MAX) cand[p] = f;
        } else if (v > Tval) nhi_loc++;
    }
    atomicAdd(&s_nhi, nhi_loc);
    __syncthreads();
    const unsigned nc = s_nc;
    if (nc > CAND_MAX) return;

    for (unsigned j = 0; j < nc; j++) {
        const int f = cand[j];
        float s = 0.f, c = 0.f;
        for (int d = tid; d < DDIM; d += 256) {
            float p = __fmaf_rn(xs[d], Wi[(size_t)d * FDIM + f], 0.f);
            float y = __fsub_rn(p, c);
            float t2 = __fadd_rn(s, y);
            c = __fsub_rn(__fsub_rn(t2, s), y);
            s = t2;
        }
        red[tid] = s;
        __syncthreads();
        for (int o = 128; o > 0; o >>= 1) {
            if (tid < o) red[tid] = __fadd_rn(red[tid], red[tid + o]);
            __syncthreads();
        }
        if (tid == 0) {
            float v = __fadd_rn(red[0], bi[f]);
            cex[j] = (v > 0.f) ? v : 0.f;
        }
        __syncthreads();
    }
    if (tid != 0) return;

    float* srow = sparse + (size_t)row * FDIM;
    float* vrow = g_vals + row * KSEL;
    int*   irow = g_idx  + row * KSEL;

    int k_rem = KSEL - (int)s_nhi;
    bool want[CAND_MAX], cur[CAND_MAX];
    for (unsigned j = 0; j < nc; j++) {
        want[j] = false;
        cur[j] = (srow[cand[j]] != 0.f);
    }
    for (int slot = 0; slot < k_rem; slot++) {
        int best = -1;
        for (unsigned j = 0; j < nc; j++) {
            if (want[j]) continue;
            if (best < 0 || cex[j] > cex[best] ||
                (cex[j] == cex[best] && cand[j] < cand[best])) best = (int)j;
        }
        if (best >= 0) want[best] = true;
    }
    int addq[CAND_MAX]; int na = 0;
    for (unsigned j = 0; j < nc; j++) if (want[j] && !cur[j]) addq[na++] = (int)j;
    int ai = 0;
    for (unsigned j = 0; j < nc && ai < na; j++) {
        if (cur[j] && !want[j]) {
            int rf = cand[j];
            int af = cand[addq[ai]]; ai++;
            float av = hrow[af];
            srow[rf] = 0.f;
            srow[af] = av;
            for (int q = 0; q < KSEL; q++)
                if (irow[q] == rf) { irow[q] = af; vrow[q] = av; break; }
        }
    }
}

// ---- classifier ---------------------------------------------------------------------
__global__ void __launch_bounds__(256) cls_kernel(
    const float* __restrict__ Wc, const float* __restrict__ bc,
    float* __restrict__ logits)
{
    const int row = blockIdx.x;
    const int tid = threadIdx.x;
    __shared__ float sv[KSEL];
    __shared__ int   si[KSEL];
    if (tid < KSEL) {
        sv[tid] = g_vals[row * KSEL + tid];
        si[tid] = g_idx [row * KSEL + tid];
    }
    __syncthreads();
    if (tid >= 250) return;
    const int c = tid * 4;
    float4 acc = *(const float4*)&bc[c];
#pragma unroll 4
    for (int j = 0; j < KSEL; j++) {
        const float v = sv[j];
        const float4 w = *(const float4*)&Wc[(size_t)si[j] * CDIM + c];
        acc.x = fmaf(v, w.x, acc.x);
        acc.y = fmaf(v, w.y, acc.y);
        acc.z = fmaf(v, w.z, acc.z);
        acc.w = fmaf(v, w.w, acc.w);
    }
    *(float4*)&logits[(size_t)row * CDIM + c] = acc;
}

// ----------------------------------------------------------------------------------------
extern "C" void kernel_launch(void* const* d_in, const int* in_sizes, int n_in,
                              void* d_out, int out_size)
{
    const float* x  = (const float*)d_in[0];
    const float* Wi = (const float*)d_in[1];
    const float* bi = (const float*)d_in[2];
    const float* Wc = (const float*)d_in[3];
    const float* bc = (const float*)d_in[4];
    (void)in_sizes; (void)n_in; (void)out_size;

    float* sparse = (float*)d_out;
    float* logits = (float*)d_out + (size_t)BDIM * FDIM;

    static int smem_set = 0;
    if (!smem_set) {
        cudaFuncSetAttribute(mma_gemm, cudaFuncAttributeMaxDynamicSharedMemorySize, SMEMDYN);
        smem_set = 1;
    }

    split_A<<<2048, 256>>>(x);
    split_BT<<<dim3(FDIM / 32, DDIM / 32), 256>>>(Wi);
    mma_gemm<<<dim3(FDIM / 128, BDIM / 128), 256, SMEMDYN>>>(bi);
    topk_kernel<<<BDIM, 256>>>(sparse);
    repair_kernel<<<MAXFLAG, 256>>>(x, Wi, bi, sparse);
    cls_kernel<<<BDIM, 256>>>(Wc, bc, logits);
}